// round 6
// baseline (speedup 1.0000x reference)
#include <cuda_runtime.h>
#include <math.h>

// ---------------------------------------------------------------------------
// Problem constants
//   x: (8, 256, 32, 32)  -> [b][c][s], s = 1024
//   w_qkv: (1536, 256)   row-major
//   w_out: (256, 512)    row-major
//   b_out: (256,)
//   HEADS=8, DIM_HEAD=64, SCALE=10, ROT_DIM=32 (16 freqs)
//   NOTE: reference L2-normalizes q,k over the SEQUENCE axis (s=1024),
//   per (b, h, d) row — not over the head dim.
// ---------------------------------------------------------------------------
#define B_   8
#define C_   256
#define S_   1024
#define H_   8
#define D_   64
#define HID_ 512           // H_*D_
#define O1_  1536          // 3*HID_

// Scratch (device globals; no allocation allowed)
__device__ float g_qkv[B_ * O1_ * S_];     // [b][o][s]   48 MB
__device__ float g_att[B_ * HID_ * S_];    // [b][h*64+d][s]  16 MB
__device__ float g_sin[S_ * 16];
__device__ float g_cos[S_ * 16];

// ---------------------------------------------------------------------------
// 0) sin/cos table (double-precision reference-accurate, cheap)
// ---------------------------------------------------------------------------
__global__ void init_tab_kernel() {
    int id = blockIdx.x * blockDim.x + threadIdx.x;   // 16384
    if (id >= S_ * 16) return;
    int s = id >> 4;
    int j = id & 15;
    // inv_freq = 10000^(-j/16), rounded to fp32 like the reference
    float invf = (float)pow(10000.0, -(double)j / 16.0);
    double ang = (double)s * (double)invf;
    g_sin[id] = (float)sin(ang);
    g_cos[id] = (float)cos(ang);
}

// ---------------------------------------------------------------------------
// 1) QKV GEMM:  C[b,o,s] = sum_c W[o,c] * X[b,c,s]
//    64x64 tile, k-tile 16, 256 threads, 4x4 micro-tile
//    grid: (S_/64=16, O1_/64=24, B_=8)
// ---------------------------------------------------------------------------
__global__ __launch_bounds__(256) void qkv_gemm_kernel(
    const float* __restrict__ W, const float* __restrict__ X,
    float* __restrict__ C)
{
    __shared__ float Ws[16 * 65];   // [kk][o], stride 65 (bank pad)
    __shared__ float Xs[16 * 64];   // [kk][s]

    const int tid = threadIdx.x;
    const int tx = tid & 15, ty = tid >> 4;
    const int s0 = blockIdx.x * 64;
    const int o0 = blockIdx.y * 64;
    const int b  = blockIdx.z;

    const float* Wp = W + (size_t)o0 * 256;
    const float* Xp = X + (size_t)b * 256 * S_ + s0;

    const int w_oo = tid >> 2, w_cq = tid & 3;    // W loader: 64 rows x 4 quads
    const int x_cc = tid >> 4, x_sq = tid & 15;   // X loader: 16 rows x 16 quads

    float acc[4][4] = {};

    for (int k0 = 0; k0 < 256; k0 += 16) {
        float4 w4 = *(const float4*)(Wp + (size_t)w_oo * 256 + k0 + w_cq * 4);
        float4 x4 = *(const float4*)(Xp + (size_t)(k0 + x_cc) * S_ + x_sq * 4);
        __syncthreads();
        Ws[(w_cq * 4 + 0) * 65 + w_oo] = w4.x;
        Ws[(w_cq * 4 + 1) * 65 + w_oo] = w4.y;
        Ws[(w_cq * 4 + 2) * 65 + w_oo] = w4.z;
        Ws[(w_cq * 4 + 3) * 65 + w_oo] = w4.w;
        *(float4*)&Xs[x_cc * 64 + x_sq * 4] = x4;
        __syncthreads();
#pragma unroll
        for (int kk = 0; kk < 16; kk++) {
            float a0 = Ws[kk * 65 + ty * 4 + 0];
            float a1 = Ws[kk * 65 + ty * 4 + 1];
            float a2 = Ws[kk * 65 + ty * 4 + 2];
            float a3 = Ws[kk * 65 + ty * 4 + 3];
            float4 b4 = *(float4*)&Xs[kk * 64 + tx * 4];
            acc[0][0] += a0 * b4.x; acc[0][1] += a0 * b4.y; acc[0][2] += a0 * b4.z; acc[0][3] += a0 * b4.w;
            acc[1][0] += a1 * b4.x; acc[1][1] += a1 * b4.y; acc[1][2] += a1 * b4.z; acc[1][3] += a1 * b4.w;
            acc[2][0] += a2 * b4.x; acc[2][1] += a2 * b4.y; acc[2][2] += a2 * b4.z; acc[2][3] += a2 * b4.w;
            acc[3][0] += a3 * b4.x; acc[3][1] += a3 * b4.y; acc[3][2] += a3 * b4.z; acc[3][3] += a3 * b4.w;
        }
    }

    float* Cp = C + ((size_t)b * O1_ + o0) * S_ + s0;
#pragma unroll
    for (int ii = 0; ii < 4; ii++) {
        float4 r = make_float4(acc[ii][0], acc[ii][1], acc[ii][2], acc[ii][3]);
        *(float4*)(Cp + (size_t)(ty * 4 + ii) * S_ + tx * 4) = r;
    }
}

// ---------------------------------------------------------------------------
// 2a) RoPE on Q and K (in place). Rotates only d in [0,32).
//     One thread per (qk, b, h, s); s consecutive within warp -> coalesced.
// ---------------------------------------------------------------------------
__global__ __launch_bounds__(256) void rope_kernel(float* __restrict__ qkv)
{
    int gid = blockIdx.x * blockDim.x + threadIdx.x;   // 131072 total
    int s  = gid & 1023;
    int r  = gid >> 10;      // 0..127
    int h  = r & 7;
    int b  = (r >> 3) & 7;
    int qk = r >> 6;         // 0 = Q, 1 = K

    float* p = qkv + ((size_t)b * O1_ + qk * HID_ + h * D_) * S_ + s;

    const float* sp = &g_sin[s * 16];
    const float* cp = &g_cos[s * 16];
#pragma unroll
    for (int d = 0; d < 16; d++) {
        float c  = cp[d];
        float sn = sp[d];
        float x = p[(size_t)d * S_];
        float y = p[(size_t)(d + 16) * S_];
        p[(size_t)d * S_]        = x * c - y * sn;
        p[(size_t)(d + 16) * S_] = y * c + x * sn;
    }
}

// ---------------------------------------------------------------------------
// 2b) L2 norm over the SEQUENCE axis: each (b, o) row of q,k (o in [0,1024))
//     is divided by its norm over the 1024 s-positions.
//     One block per row; 256 threads x float4 = 1024 elements.
// ---------------------------------------------------------------------------
__global__ __launch_bounds__(256) void l2norm_kernel(float* __restrict__ qkv)
{
    int row = blockIdx.x;          // 0 .. 8*1024-1
    int b = row >> 10;
    int o = row & 1023;            // q+k channel within this batch
    float* p = qkv + ((size_t)b * O1_ + o) * S_;

    int tid = threadIdx.x;
    float4 v = *(float4*)(p + tid * 4);
    float ss = v.x * v.x + v.y * v.y + v.z * v.z + v.w * v.w;
#pragma unroll
    for (int off = 16; off; off >>= 1)
        ss += __shfl_xor_sync(0xffffffffu, ss, off);

    __shared__ float wss[8];
    if ((tid & 31) == 0) wss[tid >> 5] = ss;
    __syncthreads();
    if (tid < 32) {
        float t = (tid < 8) ? wss[tid] : 0.f;
#pragma unroll
        for (int off = 4; off; off >>= 1)
            t += __shfl_xor_sync(0xffffffffu, t, off);
        if (tid == 0) wss[0] = t;
    }
    __syncthreads();

    float inv = 1.0f / fmaxf(sqrtf(wss[0]), 1e-12f);
    v.x *= inv; v.y *= inv; v.z *= inv; v.w *= inv;
    *(float4*)(p + tid * 4) = v;
}

// ---------------------------------------------------------------------------
// 3) Attention per (b,h):  sim = 10 * Q^T K ; softmax (no max needed: after
//    the s-axis l2norm, |sim| <= ||q_col||*||k_col|| which is O(1/16) for
//    this data; exp(10*sim) is fp32-safe) ; O = attn @ V^T.
//    Block: 256 threads, i-tile 64, j-tile 64.
//    grid: (16 i-tiles, 8 heads, 8 batch)
// ---------------------------------------------------------------------------
#define ATTN_SMEM_FLOATS (4096 * 3 + 4160)

__global__ __launch_bounds__(256) void attn_kernel(
    const float* __restrict__ qkv, float* __restrict__ att)
{
    extern __shared__ float sm[];
    float* Qs = sm;            // [d][i]  64x64
    float* Ks = Qs + 4096;     // [d][j]  64x64
    float* Vs = Ks + 4096;     // [d][j]  64x64
    float* Ps = Vs + 4096;     // [i][j]  64x64 (reused as [d][i] stride-65)

    const int tid = threadIdx.x;
    const int tx = tid & 15, ty = tid >> 4;
    const int i0 = blockIdx.x * 64;
    const int h  = blockIdx.y;
    const int b  = blockIdx.z;

    const float* Qg = qkv + ((size_t)b * O1_ + h * D_) * S_;
    const float* Kg = Qg + (size_t)HID_ * S_;
    const float* Vg = Qg + (size_t)(2 * HID_) * S_;

    // Load Q tile [d][i0..i0+63]
    for (int v = tid; v < 1024; v += 256) {
        int d = v >> 4, iq = v & 15;
        *(float4*)&Qs[d * 64 + iq * 4] =
            *(const float4*)(Qg + (size_t)d * S_ + i0 + iq * 4);
    }

    float o_acc[4][4] = {};
    float l_acc[4]    = {0.f, 0.f, 0.f, 0.f};

    for (int j0 = 0; j0 < S_; j0 += 64) {
        __syncthreads();
        for (int v = tid; v < 1024; v += 256) {
            int d = v >> 4, jq = v & 15;
            *(float4*)&Ks[d * 64 + jq * 4] =
                *(const float4*)(Kg + (size_t)d * S_ + j0 + jq * 4);
            *(float4*)&Vs[d * 64 + jq * 4] =
                *(const float4*)(Vg + (size_t)d * S_ + j0 + jq * 4);
        }
        __syncthreads();

        // S tile: sacc[ii][jj] = sum_d Qs[d][ty*4+ii] * Ks[d][tx*4+jj]
        float sacc[4][4] = {};
#pragma unroll 16
        for (int d = 0; d < 64; d++) {
            float4 a4 = *(float4*)&Qs[d * 64 + ty * 4];
            float4 b4 = *(float4*)&Ks[d * 64 + tx * 4];
            sacc[0][0] += a4.x * b4.x; sacc[0][1] += a4.x * b4.y; sacc[0][2] += a4.x * b4.z; sacc[0][3] += a4.x * b4.w;
            sacc[1][0] += a4.y * b4.x; sacc[1][1] += a4.y * b4.y; sacc[1][2] += a4.y * b4.z; sacc[1][3] += a4.y * b4.w;
            sacc[2][0] += a4.z * b4.x; sacc[2][1] += a4.z * b4.y; sacc[2][2] += a4.z * b4.z; sacc[2][3] += a4.z * b4.w;
            sacc[3][0] += a4.w * b4.x; sacc[3][1] += a4.w * b4.y; sacc[3][2] += a4.w * b4.z; sacc[3][3] += a4.w * b4.w;
        }

        // P = exp(10*S); accumulate row sums; stage P to smem
#pragma unroll
        for (int ii = 0; ii < 4; ii++) {
            float p0 = __expf(10.f * sacc[ii][0]);
            float p1 = __expf(10.f * sacc[ii][1]);
            float p2 = __expf(10.f * sacc[ii][2]);
            float p3 = __expf(10.f * sacc[ii][3]);
            l_acc[ii] += (p0 + p1) + (p2 + p3);
            *(float4*)&Ps[(ty * 4 + ii) * 64 + tx * 4] = make_float4(p0, p1, p2, p3);
        }
        __syncthreads();

        // O[i][d] += sum_j P[i][j] * V[d][j]   (j rotated by tx to dodge
        // the 64-word-stride bank conflict on the Vs row reads)
#pragma unroll
        for (int jj4 = 0; jj4 < 64; jj4 += 4) {
            int j = (jj4 + tx * 4) & 63;
            float4 a0 = *(float4*)&Ps[(ty * 4 + 0) * 64 + j];
            float4 a1 = *(float4*)&Ps[(ty * 4 + 1) * 64 + j];
            float4 a2 = *(float4*)&Ps[(ty * 4 + 2) * 64 + j];
            float4 a3 = *(float4*)&Ps[(ty * 4 + 3) * 64 + j];
            float4 v0 = *(float4*)&Vs[(tx * 4 + 0) * 64 + j];
            float4 v1 = *(float4*)&Vs[(tx * 4 + 1) * 64 + j];
            float4 v2 = *(float4*)&Vs[(tx * 4 + 2) * 64 + j];
            float4 v3 = *(float4*)&Vs[(tx * 4 + 3) * 64 + j];
#define DOT4(a, v) (a.x * v.x + a.y * v.y + a.z * v.z + a.w * v.w)
            o_acc[0][0] += DOT4(a0, v0); o_acc[0][1] += DOT4(a0, v1); o_acc[0][2] += DOT4(a0, v2); o_acc[0][3] += DOT4(a0, v3);
            o_acc[1][0] += DOT4(a1, v0); o_acc[1][1] += DOT4(a1, v1); o_acc[1][2] += DOT4(a1, v2); o_acc[1][3] += DOT4(a1, v3);
            o_acc[2][0] += DOT4(a2, v0); o_acc[2][1] += DOT4(a2, v1); o_acc[2][2] += DOT4(a2, v2); o_acc[2][3] += DOT4(a2, v3);
            o_acc[3][0] += DOT4(a3, v0); o_acc[3][1] += DOT4(a3, v1); o_acc[3][2] += DOT4(a3, v2); o_acc[3][3] += DOT4(a3, v3);
#undef DOT4
        }
    }

    // reduce row sums across the 16 lanes owning each row (tx dimension)
#pragma unroll
    for (int ii = 0; ii < 4; ii++) {
        float l = l_acc[ii];
        l += __shfl_xor_sync(0xffffffffu, l, 8, 16);
        l += __shfl_xor_sync(0xffffffffu, l, 4, 16);
        l += __shfl_xor_sync(0xffffffffu, l, 2, 16);
        l += __shfl_xor_sync(0xffffffffu, l, 1, 16);
        float inv = 1.0f / l;
#pragma unroll
        for (int dd = 0; dd < 4; dd++) o_acc[ii][dd] *= inv;
    }

    // transpose O[i][d] -> [d][i] via smem (stride 65), then coalesced store
    __syncthreads();
#pragma unroll
    for (int ii = 0; ii < 4; ii++)
#pragma unroll
        for (int dd = 0; dd < 4; dd++)
            Ps[(tx * 4 + dd) * 65 + ty * 4 + ii] = o_acc[ii][dd];
    __syncthreads();

    float* Ap = att + ((size_t)b * HID_ + h * D_) * S_ + i0;
    for (int v = tid; v < 4096; v += 256) {
        int d = v >> 6, i = v & 63;
        Ap[(size_t)d * S_ + i] = Ps[d * 65 + i];
    }
}

// ---------------------------------------------------------------------------
// 4) Output projection: out[b,o,s] = sum_c W2[o,c]*att[b,c,s] + bias[o]
//    Same tiling as GEMM1.  grid: (16, 4, 8)
// ---------------------------------------------------------------------------
__global__ __launch_bounds__(256) void out_gemm_kernel(
    const float* __restrict__ W, const float* __restrict__ X,
    const float* __restrict__ bias, float* __restrict__ Cout)
{
    __shared__ float Ws[16 * 65];
    __shared__ float Xs[16 * 64];

    const int tid = threadIdx.x;
    const int tx = tid & 15, ty = tid >> 4;
    const int s0 = blockIdx.x * 64;
    const int o0 = blockIdx.y * 64;
    const int b  = blockIdx.z;

    const float* Wp = W + (size_t)o0 * HID_;
    const float* Xp = X + (size_t)b * HID_ * S_ + s0;

    const int w_oo = tid >> 2, w_cq = tid & 3;
    const int x_cc = tid >> 4, x_sq = tid & 15;

    float acc[4][4] = {};

    for (int k0 = 0; k0 < HID_; k0 += 16) {
        float4 w4 = *(const float4*)(Wp + (size_t)w_oo * HID_ + k0 + w_cq * 4);
        float4 x4 = *(const float4*)(Xp + (size_t)(k0 + x_cc) * S_ + x_sq * 4);
        __syncthreads();
        Ws[(w_cq * 4 + 0) * 65 + w_oo] = w4.x;
        Ws[(w_cq * 4 + 1) * 65 + w_oo] = w4.y;
        Ws[(w_cq * 4 + 2) * 65 + w_oo] = w4.z;
        Ws[(w_cq * 4 + 3) * 65 + w_oo] = w4.w;
        *(float4*)&Xs[x_cc * 64 + x_sq * 4] = x4;
        __syncthreads();
#pragma unroll
        for (int kk = 0; kk < 16; kk++) {
            float a0 = Ws[kk * 65 + ty * 4 + 0];
            float a1 = Ws[kk * 65 + ty * 4 + 1];
            float a2 = Ws[kk * 65 + ty * 4 + 2];
            float a3 = Ws[kk * 65 + ty * 4 + 3];
            float4 b4 = *(float4*)&Xs[kk * 64 + tx * 4];
            acc[0][0] += a0 * b4.x; acc[0][1] += a0 * b4.y; acc[0][2] += a0 * b4.z; acc[0][3] += a0 * b4.w;
            acc[1][0] += a1 * b4.x; acc[1][1] += a1 * b4.y; acc[1][2] += a1 * b4.z; acc[1][3] += a1 * b4.w;
            acc[2][0] += a2 * b4.x; acc[2][1] += a2 * b4.y; acc[2][2] += a2 * b4.z; acc[2][3] += a2 * b4.w;
            acc[3][0] += a3 * b4.x; acc[3][1] += a3 * b4.y; acc[3][2] += a3 * b4.z; acc[3][3] += a3 * b4.w;
        }
    }

    float* Cp = Cout + ((size_t)b * C_ + o0) * S_ + s0;
#pragma unroll
    for (int ii = 0; ii < 4; ii++) {
        float bv = bias[o0 + ty * 4 + ii];
        float4 r = make_float4(acc[ii][0] + bv, acc[ii][1] + bv,
                               acc[ii][2] + bv, acc[ii][3] + bv);
        *(float4*)(Cp + (size_t)(ty * 4 + ii) * S_ + tx * 4) = r;
    }
}

// ---------------------------------------------------------------------------
// Launch
// ---------------------------------------------------------------------------
extern "C" void kernel_launch(void* const* d_in, const int* in_sizes, int n_in,
                              void* d_out, int out_size)
{
    const float* x     = (const float*)d_in[0];  // (8,256,32,32)
    const float* w_qkv = (const float*)d_in[1];  // (1536,256)
    const float* w_out = (const float*)d_in[2];  // (256,512)
    const float* b_out = (const float*)d_in[3];  // (256,)
    float* out = (float*)d_out;

    float* qkv; cudaGetSymbolAddress((void**)&qkv, g_qkv);
    float* att; cudaGetSymbolAddress((void**)&att, g_att);

    // opt-in to >48KB dynamic smem for the attention kernel (idempotent)
    static const size_t attn_smem = ATTN_SMEM_FLOATS * sizeof(float);
    cudaFuncSetAttribute(attn_kernel,
                         cudaFuncAttributeMaxDynamicSharedMemorySize,
                         (int)attn_smem);

    // 0) sin/cos table
    init_tab_kernel<<<(S_ * 16 + 255) / 256, 256>>>();

    // 1) QKV GEMM
    {
        dim3 grid(S_ / 64, O1_ / 64, B_);
        qkv_gemm_kernel<<<grid, 256>>>(w_qkv, x, qkv);
    }

    // 2a) RoPE on Q,K (in place)
    rope_kernel<<<(2 * B_ * H_ * S_) / 256, 256>>>(qkv);

    // 2b) L2 norm over sequence axis for all q,k rows (8 b x 1024 channels)
    l2norm_kernel<<<B_ * 2 * HID_, 256>>>(qkv);

    // 3) Attention
    {
        dim3 grid(S_ / 64, H_, B_);
        attn_kernel<<<grid, 256, attn_smem>>>(qkv, att);
    }

    // 4) Output projection + bias
    {
        dim3 grid(S_ / 64, C_ / 64, B_);
        out_gemm_kernel<<<grid, 256>>>(w_out, att, b_out, out);
    }
}

// round 7
// speedup vs baseline: 1.5521x; 1.5521x over previous
#include <cuda_runtime.h>
#include <math.h>
#include <stdint.h>

// ---------------------------------------------------------------------------
// Problem constants
//   x: (8, 256, 32, 32)  -> [b][c][s], s = 1024
//   w_qkv: (1536, 256), w_out: (256, 512), b_out: (256,)
//   HEADS=8, DIM_HEAD=64, SCALE=10, ROT_DIM=32 (16 freqs)
//   L2 norm is over the SEQUENCE axis (per (b,h,d) row), per reference.
// ---------------------------------------------------------------------------
#define B_   8
#define C_   256
#define S_   1024
#define H_   8
#define D_   64
#define HID_ 512
#define O1_  1536

__device__ float g_qkv[B_ * O1_ * S_];     // [b][o][s]
__device__ float g_att[B_ * HID_ * S_];    // [b][h*64+d][s]
__device__ float g_sin[S_ * 16];
__device__ float g_cos[S_ * 16];

// ---------------------------------------------------------------------------
// 0) sin/cos table
// ---------------------------------------------------------------------------
__global__ void init_tab_kernel() {
    int id = blockIdx.x * blockDim.x + threadIdx.x;
    if (id >= S_ * 16) return;
    int s = id >> 4;
    int j = id & 15;
    float invf = (float)pow(10000.0, -(double)j / 16.0);
    double ang = (double)s * (double)invf;
    g_sin[id] = (float)sin(ang);
    g_cos[id] = (float)cos(ang);
}

// ---------------------------------------------------------------------------
// 1) QKV GEMM (fp32): C[b,o,s] = sum_c W[o,c] * X[b,c,s]
// ---------------------------------------------------------------------------
__global__ __launch_bounds__(256) void qkv_gemm_kernel(
    const float* __restrict__ W, const float* __restrict__ X,
    float* __restrict__ C)
{
    __shared__ float Ws[16 * 65];
    __shared__ float Xs[16 * 64];

    const int tid = threadIdx.x;
    const int tx = tid & 15, ty = tid >> 4;
    const int s0 = blockIdx.x * 64;
    const int o0 = blockIdx.y * 64;
    const int b  = blockIdx.z;

    const float* Wp = W + (size_t)o0 * 256;
    const float* Xp = X + (size_t)b * 256 * S_ + s0;

    const int w_oo = tid >> 2, w_cq = tid & 3;
    const int x_cc = tid >> 4, x_sq = tid & 15;

    float acc[4][4] = {};

    for (int k0 = 0; k0 < 256; k0 += 16) {
        float4 w4 = *(const float4*)(Wp + (size_t)w_oo * 256 + k0 + w_cq * 4);
        float4 x4 = *(const float4*)(Xp + (size_t)(k0 + x_cc) * S_ + x_sq * 4);
        __syncthreads();
        Ws[(w_cq * 4 + 0) * 65 + w_oo] = w4.x;
        Ws[(w_cq * 4 + 1) * 65 + w_oo] = w4.y;
        Ws[(w_cq * 4 + 2) * 65 + w_oo] = w4.z;
        Ws[(w_cq * 4 + 3) * 65 + w_oo] = w4.w;
        *(float4*)&Xs[x_cc * 64 + x_sq * 4] = x4;
        __syncthreads();
#pragma unroll
        for (int kk = 0; kk < 16; kk++) {
            float a0 = Ws[kk * 65 + ty * 4 + 0];
            float a1 = Ws[kk * 65 + ty * 4 + 1];
            float a2 = Ws[kk * 65 + ty * 4 + 2];
            float a3 = Ws[kk * 65 + ty * 4 + 3];
            float4 b4 = *(float4*)&Xs[kk * 64 + tx * 4];
            acc[0][0] += a0 * b4.x; acc[0][1] += a0 * b4.y; acc[0][2] += a0 * b4.z; acc[0][3] += a0 * b4.w;
            acc[1][0] += a1 * b4.x; acc[1][1] += a1 * b4.y; acc[1][2] += a1 * b4.z; acc[1][3] += a1 * b4.w;
            acc[2][0] += a2 * b4.x; acc[2][1] += a2 * b4.y; acc[2][2] += a2 * b4.z; acc[2][3] += a2 * b4.w;
            acc[3][0] += a3 * b4.x; acc[3][1] += a3 * b4.y; acc[3][2] += a3 * b4.z; acc[3][3] += a3 * b4.w;
        }
    }

    float* Cp = C + ((size_t)b * O1_ + o0) * S_ + s0;
#pragma unroll
    for (int ii = 0; ii < 4; ii++) {
        float4 r = make_float4(acc[ii][0], acc[ii][1], acc[ii][2], acc[ii][3]);
        *(float4*)(Cp + (size_t)(ty * 4 + ii) * S_ + tx * 4) = r;
    }
}

// ---------------------------------------------------------------------------
// 2a) RoPE (in place)
// ---------------------------------------------------------------------------
__global__ __launch_bounds__(256) void rope_kernel(float* __restrict__ qkv)
{
    int gid = blockIdx.x * blockDim.x + threadIdx.x;
    int s  = gid & 1023;
    int r  = gid >> 10;
    int h  = r & 7;
    int b  = (r >> 3) & 7;
    int qk = r >> 6;

    float* p = qkv + ((size_t)b * O1_ + qk * HID_ + h * D_) * S_ + s;
    const float* sp = &g_sin[s * 16];
    const float* cp = &g_cos[s * 16];
#pragma unroll
    for (int d = 0; d < 16; d++) {
        float c  = cp[d];
        float sn = sp[d];
        float x = p[(size_t)d * S_];
        float y = p[(size_t)(d + 16) * S_];
        p[(size_t)d * S_]        = x * c - y * sn;
        p[(size_t)(d + 16) * S_] = y * c + x * sn;
    }
}

// ---------------------------------------------------------------------------
// 2b) L2 norm over the sequence axis (per q,k channel row)
// ---------------------------------------------------------------------------
__global__ __launch_bounds__(256) void l2norm_kernel(float* __restrict__ qkv)
{
    int row = blockIdx.x;
    int b = row >> 10;
    int o = row & 1023;
    float* p = qkv + ((size_t)b * O1_ + o) * S_;

    int tid = threadIdx.x;
    float4 v = *(float4*)(p + tid * 4);
    float ss = v.x * v.x + v.y * v.y + v.z * v.z + v.w * v.w;
#pragma unroll
    for (int off = 16; off; off >>= 1)
        ss += __shfl_xor_sync(0xffffffffu, ss, off);

    __shared__ float wss[8];
    if ((tid & 31) == 0) wss[tid >> 5] = ss;
    __syncthreads();
    if (tid < 32) {
        float t = (tid < 8) ? wss[tid] : 0.f;
#pragma unroll
        for (int off = 4; off; off >>= 1)
            t += __shfl_xor_sync(0xffffffffu, t, off);
        if (tid == 0) wss[0] = t;
    }
    __syncthreads();

    float inv = 1.0f / fmaxf(sqrtf(wss[0]), 1e-12f);
    v.x *= inv; v.y *= inv; v.z *= inv; v.w *= inv;
    *(float4*)(p + tid * 4) = v;
}

// ---------------------------------------------------------------------------
// 3) Attention (tf32 tensor-core): per (b,h)
//    S = 10 * Q^T K ; P = exp(S) (no max needed, |S|<=~1) ; O = P V^T / rowsum
//    Block tile: i=64, j-iter=128.  8 warps.
//      S phase: warp grid 2(i) x 4(j), warp tile 32x32 (2m x 4n, k8)
//      O phase: warp grid 2(i) x 4(d), warp tile 32x16 (2m x 2n, k8)
//    mma.sync.m16n8k8 tf32 (fp32 operands truncated by HW; acceptable error).
//
//    smem (floats):
//      Qs [d=64][i=64]  stride 68   @ 0       (reused as Ot[d][i] at the end)
//      Ks [d=64][j=128] stride 132  @ 4352
//      Vs [d=64][j=128] stride 132  @ 12800
//      Ps [j=128][i=64] stride 68   @ 21248
//      l  [64]                      @ 29952
// ---------------------------------------------------------------------------
#define AT_QS 0
#define AT_KS 4352
#define AT_VS 12800
#define AT_PS 21248
#define AT_L  29952
#define AT_SMEM_FLOATS 30016

__device__ __forceinline__ void mma_tf32(float c[4],
    uint32_t a0, uint32_t a1, uint32_t a2, uint32_t a3,
    uint32_t b0, uint32_t b1)
{
    asm volatile(
        "mma.sync.aligned.m16n8k8.row.col.f32.tf32.tf32.f32 "
        "{%0,%1,%2,%3}, {%4,%5,%6,%7}, {%8,%9}, {%0,%1,%2,%3};"
        : "+f"(c[0]), "+f"(c[1]), "+f"(c[2]), "+f"(c[3])
        : "r"(a0), "r"(a1), "r"(a2), "r"(a3), "r"(b0), "r"(b1));
}

__global__ __launch_bounds__(256) void attn_tc_kernel(
    const float* __restrict__ qkv, float* __restrict__ att)
{
    extern __shared__ float sm[];
    float* Qs  = sm + AT_QS;
    float* Ks  = sm + AT_KS;
    float* Vs  = sm + AT_VS;
    float* Ps  = sm + AT_PS;
    float* Lsm = sm + AT_L;

    const int tid  = threadIdx.x;
    const int lane = tid & 31;
    const int warp = tid >> 5;
    const int g  = lane >> 2;       // 0..7
    const int tg = lane & 3;        // 0..3
    const int wi = warp & 1;        // i-half (shared by S and O phases)
    const int wq = warp >> 1;       // j-quarter (S) / d-quarter (O)
    const int ib = wi * 32;

    const int i0 = blockIdx.x * 64;
    const int h  = blockIdx.y;
    const int b  = blockIdx.z;

    const float* Qg = qkv + ((size_t)b * O1_ + h * D_) * S_;
    const float* Kg = Qg + (size_t)HID_ * S_;
    const float* Vg = Qg + (size_t)(2 * HID_) * S_;

    // Load Q tile [d][i] (i0..i0+63), stride 68
    for (int v = tid; v < 1024; v += 256) {
        int d = v >> 4, iq = v & 15;
        *(float4*)&Qs[d * 68 + iq * 4] =
            *(const float4*)(Qg + (size_t)d * S_ + i0 + iq * 4);
    }
    if (tid < 64) Lsm[tid] = 0.f;

    float oacc[2][2][4] = {};
    float l_acc[2][2]   = {};

    for (int j0 = 0; j0 < S_; j0 += 128) {
        __syncthreads();   // prev Ps/Vs consumed; Q/Lsm visible on first iter
        // Load K,V tiles [d][j0..j0+127], stride 132
        for (int v = tid; v < 2048; v += 256) {
            int d = v >> 5, jq = v & 31;
            *(float4*)&Ks[d * 132 + jq * 4] =
                *(const float4*)(Kg + (size_t)d * S_ + j0 + jq * 4);
            *(float4*)&Vs[d * 132 + jq * 4] =
                *(const float4*)(Vg + (size_t)d * S_ + j0 + jq * 4);
        }
        __syncthreads();

        // ---- S phase: warp (wi, wq) computes S[ib..ib+31][wq*32..+31]
        const int jb = wq * 32;
        float sacc[2][4][4] = {};
#pragma unroll
        for (int kk = 0; kk < 8; kk++) {
            const int k0 = kk * 8;
            uint32_t a[2][4];
#pragma unroll
            for (int mt = 0; mt < 2; mt++) {
                int r = ib + mt * 16 + g;
                a[mt][0] = __float_as_uint(Qs[(k0 + tg) * 68 + r]);
                a[mt][1] = __float_as_uint(Qs[(k0 + tg) * 68 + r + 8]);
                a[mt][2] = __float_as_uint(Qs[(k0 + tg + 4) * 68 + r]);
                a[mt][3] = __float_as_uint(Qs[(k0 + tg + 4) * 68 + r + 8]);
            }
            uint32_t bb[4][2];
#pragma unroll
            for (int nt = 0; nt < 4; nt++) {
                int jc = jb + nt * 8 + g;
                bb[nt][0] = __float_as_uint(Ks[(k0 + tg) * 132 + jc]);
                bb[nt][1] = __float_as_uint(Ks[(k0 + tg + 4) * 132 + jc]);
            }
#pragma unroll
            for (int mt = 0; mt < 2; mt++)
#pragma unroll
                for (int nt = 0; nt < 4; nt++)
                    mma_tf32(sacc[mt][nt], a[mt][0], a[mt][1], a[mt][2], a[mt][3],
                             bb[nt][0], bb[nt][1]);
        }

        // ---- exp + stage P to smem [j][i] (conflict-free banks: 8tg+4c+g)
#pragma unroll
        for (int mt = 0; mt < 2; mt++)
#pragma unroll
            for (int nt = 0; nt < 4; nt++)
#pragma unroll
                for (int c = 0; c < 4; c++) {
                    float p = __expf(10.f * sacc[mt][nt][c]);
                    int row = ib + mt * 16 + g + ((c >> 1) << 3);
                    int col = jb + nt * 8 + tg * 2 + (c & 1);
                    l_acc[mt][c >> 1] += p;
                    Ps[col * 68 + row] = p;
                }
        __syncthreads();

        // ---- O phase: warp (wi, wq) computes O[ib..ib+31][wq*16..+15]
        const int db = wq * 16;
#pragma unroll
        for (int kk = 0; kk < 16; kk++) {
            const int k0 = kk * 8;
            uint32_t a[2][4];
#pragma unroll
            for (int mt = 0; mt < 2; mt++) {
                int r = ib + mt * 16 + g;
                a[mt][0] = __float_as_uint(Ps[(k0 + tg) * 68 + r]);
                a[mt][1] = __float_as_uint(Ps[(k0 + tg) * 68 + r + 8]);
                a[mt][2] = __float_as_uint(Ps[(k0 + tg + 4) * 68 + r]);
                a[mt][3] = __float_as_uint(Ps[(k0 + tg + 4) * 68 + r + 8]);
            }
            uint32_t bb[2][2];
#pragma unroll
            for (int nt = 0; nt < 2; nt++) {
                int dc = db + nt * 8 + g;
                bb[nt][0] = __float_as_uint(Vs[dc * 132 + k0 + tg]);
                bb[nt][1] = __float_as_uint(Vs[dc * 132 + k0 + tg + 4]);
            }
#pragma unroll
            for (int mt = 0; mt < 2; mt++)
#pragma unroll
                for (int nt = 0; nt < 2; nt++)
                    mma_tf32(oacc[mt][nt], a[mt][0], a[mt][1], a[mt][2], a[mt][3],
                             bb[nt][0], bb[nt][1]);
        }
    }

    // ---- merge row sums: intra-warp over tg, cross-warp (4 j-warps) via smem
#pragma unroll
    for (int mt = 0; mt < 2; mt++)
#pragma unroll
        for (int rh = 0; rh < 2; rh++) {
            float l = l_acc[mt][rh];
            l += __shfl_xor_sync(0xffffffffu, l, 1);
            l += __shfl_xor_sync(0xffffffffu, l, 2);
            if (tg == 0)
                atomicAdd(&Lsm[ib + mt * 16 + rh * 8 + g], l);
        }
    __syncthreads();

    // ---- normalize O, write transposed [d][i] into Qs (free now), store
    const int db = wq * 16;
#pragma unroll
    for (int mt = 0; mt < 2; mt++) {
        float inv0 = 1.0f / Lsm[ib + mt * 16 + g];
        float inv1 = 1.0f / Lsm[ib + mt * 16 + 8 + g];
#pragma unroll
        for (int nt = 0; nt < 2; nt++)
#pragma unroll
            for (int c = 0; c < 4; c++) {
                float o = oacc[mt][nt][c] * ((c >> 1) ? inv1 : inv0);
                int row = ib + mt * 16 + g + ((c >> 1) << 3);
                int col = db + nt * 8 + tg * 2 + (c & 1);
                Qs[col * 68 + row] = o;     // Ot[d=col][i=row]
            }
    }
    __syncthreads();

    float* Ap = att + ((size_t)b * HID_ + h * D_) * S_ + i0;
    for (int v = tid; v < 1024; v += 256) {
        int d = v >> 4, iq = v & 15;
        *(float4*)(Ap + (size_t)d * S_ + iq * 4) = *(float4*)&Qs[d * 68 + iq * 4];
    }
}

// ---------------------------------------------------------------------------
// 4) Output projection (fp32): out[b,o,s] = sum_c W2[o,c]*att[b,c,s] + bias[o]
// ---------------------------------------------------------------------------
__global__ __launch_bounds__(256) void out_gemm_kernel(
    const float* __restrict__ W, const float* __restrict__ X,
    const float* __restrict__ bias, float* __restrict__ Cout)
{
    __shared__ float Ws[16 * 65];
    __shared__ float Xs[16 * 64];

    const int tid = threadIdx.x;
    const int tx = tid & 15, ty = tid >> 4;
    const int s0 = blockIdx.x * 64;
    const int o0 = blockIdx.y * 64;
    const int b  = blockIdx.z;

    const float* Wp = W + (size_t)o0 * HID_;
    const float* Xp = X + (size_t)b * HID_ * S_ + s0;

    const int w_oo = tid >> 2, w_cq = tid & 3;
    const int x_cc = tid >> 4, x_sq = tid & 15;

    float acc[4][4] = {};

    for (int k0 = 0; k0 < HID_; k0 += 16) {
        float4 w4 = *(const float4*)(Wp + (size_t)w_oo * HID_ + k0 + w_cq * 4);
        float4 x4 = *(const float4*)(Xp + (size_t)(k0 + x_cc) * S_ + x_sq * 4);
        __syncthreads();
        Ws[(w_cq * 4 + 0) * 65 + w_oo] = w4.x;
        Ws[(w_cq * 4 + 1) * 65 + w_oo] = w4.y;
        Ws[(w_cq * 4 + 2) * 65 + w_oo] = w4.z;
        Ws[(w_cq * 4 + 3) * 65 + w_oo] = w4.w;
        *(float4*)&Xs[x_cc * 64 + x_sq * 4] = x4;
        __syncthreads();
#pragma unroll
        for (int kk = 0; kk < 16; kk++) {
            float a0 = Ws[kk * 65 + ty * 4 + 0];
            float a1 = Ws[kk * 65 + ty * 4 + 1];
            float a2 = Ws[kk * 65 + ty * 4 + 2];
            float a3 = Ws[kk * 65 + ty * 4 + 3];
            float4 b4 = *(float4*)&Xs[kk * 64 + tx * 4];
            acc[0][0] += a0 * b4.x; acc[0][1] += a0 * b4.y; acc[0][2] += a0 * b4.z; acc[0][3] += a0 * b4.w;
            acc[1][0] += a1 * b4.x; acc[1][1] += a1 * b4.y; acc[1][2] += a1 * b4.z; acc[1][3] += a1 * b4.w;
            acc[2][0] += a2 * b4.x; acc[2][1] += a2 * b4.y; acc[2][2] += a2 * b4.z; acc[2][3] += a2 * b4.w;
            acc[3][0] += a3 * b4.x; acc[3][1] += a3 * b4.y; acc[3][2] += a3 * b4.z; acc[3][3] += a3 * b4.w;
        }
    }

    float* Cp = Cout + ((size_t)b * C_ + o0) * S_ + s0;
#pragma unroll
    for (int ii = 0; ii < 4; ii++) {
        float bv = bias[o0 + ty * 4 + ii];
        float4 r = make_float4(acc[ii][0] + bv, acc[ii][1] + bv,
                               acc[ii][2] + bv, acc[ii][3] + bv);
        *(float4*)(Cp + (size_t)(ty * 4 + ii) * S_ + tx * 4) = r;
    }
}

// ---------------------------------------------------------------------------
// Launch
// ---------------------------------------------------------------------------
extern "C" void kernel_launch(void* const* d_in, const int* in_sizes, int n_in,
                              void* d_out, int out_size)
{
    const float* x     = (const float*)d_in[0];
    const float* w_qkv = (const float*)d_in[1];
    const float* w_out = (const float*)d_in[2];
    const float* b_out = (const float*)d_in[3];
    float* out = (float*)d_out;

    float* qkv; cudaGetSymbolAddress((void**)&qkv, g_qkv);
    float* att; cudaGetSymbolAddress((void**)&att, g_att);

    static const size_t attn_smem = AT_SMEM_FLOATS * sizeof(float);  // ~120 KB
    cudaFuncSetAttribute(attn_tc_kernel,
                         cudaFuncAttributeMaxDynamicSharedMemorySize,
                         (int)attn_smem);

    init_tab_kernel<<<(S_ * 16 + 255) / 256, 256>>>();

    {
        dim3 grid(S_ / 64, O1_ / 64, B_);
        qkv_gemm_kernel<<<grid, 256>>>(w_qkv, x, qkv);
    }

    rope_kernel<<<(2 * B_ * H_ * S_) / 256, 256>>>(qkv);
    l2norm_kernel<<<B_ * 2 * HID_, 256>>>(qkv);

    {
        dim3 grid(S_ / 64, H_, B_);
        attn_tc_kernel<<<grid, 256, attn_smem>>>(qkv, att);
    }

    {
        dim3 grid(S_ / 64, C_ / 64, B_);
        out_gemm_kernel<<<grid, 256>>>(w_out, att, b_out, out);
    }
}

// round 8
// speedup vs baseline: 1.8821x; 1.2126x over previous
#include <cuda_runtime.h>
#include <math.h>
#include <stdint.h>

// ---------------------------------------------------------------------------
// Problem constants
//   x: (8, 256, 32, 32)  -> [b][c][s], s = 1024
//   w_qkv: (1536, 256), w_out: (256, 512), b_out: (256,)
//   HEADS=8, DIM_HEAD=64, SCALE=10, ROT_DIM=32 (16 freqs)
//   L2 norm is over the SEQUENCE axis (per (b,h,d) row), per reference.
// ---------------------------------------------------------------------------
#define B_   8
#define C_   256
#define S_   1024
#define H_   8
#define D_   64
#define HID_ 512
#define O1_  1536

__device__ float g_qkv[B_ * O1_ * S_];     // [b][o][s]
__device__ float g_att[B_ * HID_ * S_];    // [b][h*64+d][s]
__device__ float g_sin[S_ * 16];
__device__ float g_cos[S_ * 16];

// ---------------------------------------------------------------------------
// m16n8k8 tf32 MMA
// ---------------------------------------------------------------------------
__device__ __forceinline__ void mma_tf32(float c[4],
    uint32_t a0, uint32_t a1, uint32_t a2, uint32_t a3,
    uint32_t b0, uint32_t b1)
{
    asm volatile(
        "mma.sync.aligned.m16n8k8.row.col.f32.tf32.tf32.f32 "
        "{%0,%1,%2,%3}, {%4,%5,%6,%7}, {%8,%9}, {%0,%1,%2,%3};"
        : "+f"(c[0]), "+f"(c[1]), "+f"(c[2]), "+f"(c[3])
        : "r"(a0), "r"(a1), "r"(a2), "r"(a3), "r"(b0), "r"(b1));
}

// split v = hi + lo, hi = round-to-nearest tf32
#define SPLIT_TF32(v, H, L) do { uint32_t u_;                         \
    asm("cvt.rna.tf32.f32 %0, %1;" : "=r"(u_) : "f"(v));              \
    (H) = __uint_as_float(u_); (L) = (v) - (H); } while (0)

// ---------------------------------------------------------------------------
// 0) sin/cos table
// ---------------------------------------------------------------------------
__global__ void init_tab_kernel() {
    int id = blockIdx.x * blockDim.x + threadIdx.x;
    if (id >= S_ * 16) return;
    int s = id >> 4;
    int j = id & 15;
    float invf = (float)pow(10000.0, -(double)j / 16.0);
    double ang = (double)s * (double)invf;
    g_sin[id] = (float)sin(ang);
    g_cos[id] = (float)cos(ang);
}

// ---------------------------------------------------------------------------
// 1+4) Split-tf32 tensor-core GEMM (fp32-accurate via 3 MMAs):
//      C[b, o0+m, s0+n] = sum_k W[o0+m][k] * X[b][k][s0+n]  (+ bias)
//      Block: 64(m) x 128(n), 8 warps (2m x 4n), k-chunk 16.
//      smem: Ah/Al [k16][m64] stride 68 ; Bh/Bl [k16][n128] stride 136
//      (both fragment-read bank-conflict-free).
// ---------------------------------------------------------------------------
template<int KDIM, bool BIAS>
__global__ __launch_bounds__(256) void gemm_tc_kernel(
    const float* __restrict__ W, const float* __restrict__ X,
    const float* __restrict__ bias, float* __restrict__ C, int Mtot)
{
    __shared__ float Ah[16 * 68], Al[16 * 68];
    __shared__ float Bh[16 * 136], Bl[16 * 136];

    const int tid  = threadIdx.x;
    const int lane = tid & 31, warp = tid >> 5;
    const int g = lane >> 2, tg = lane & 3;
    const int wm = warp & 1, wn = warp >> 1;
    const int mbase = wm * 32, nbase = wn * 32;

    const int s0 = blockIdx.x * 128;
    const int o0 = blockIdx.y * 64;
    const int b  = blockIdx.z;

    const float* Wp = W + (size_t)o0 * KDIM;
    const float* Xp = X + (size_t)b * KDIM * S_ + s0;

    const int am = tid >> 2, akq = tid & 3;     // A loader: 64 rows x 4 quads
    const int bk = tid >> 5, bsq = tid & 31;    // B loader: rows bk, bk+8

    // prefetch k0 = 0
    float4 w4  = *(const float4*)(Wp + (size_t)am * KDIM + akq * 4);
    float4 x4a = *(const float4*)(Xp + (size_t)bk * S_ + bsq * 4);
    float4 x4b = *(const float4*)(Xp + (size_t)(bk + 8) * S_ + bsq * 4);

    float acc[2][4][4] = {};

    for (int k0 = 0; k0 < KDIM; k0 += 16) {
        __syncthreads();
        {   // store A split, transposed [k][m]
            float h, l;
            SPLIT_TF32(w4.x, h, l); Ah[(akq * 4 + 0) * 68 + am] = h; Al[(akq * 4 + 0) * 68 + am] = l;
            SPLIT_TF32(w4.y, h, l); Ah[(akq * 4 + 1) * 68 + am] = h; Al[(akq * 4 + 1) * 68 + am] = l;
            SPLIT_TF32(w4.z, h, l); Ah[(akq * 4 + 2) * 68 + am] = h; Al[(akq * 4 + 2) * 68 + am] = l;
            SPLIT_TF32(w4.w, h, l); Ah[(akq * 4 + 3) * 68 + am] = h; Al[(akq * 4 + 3) * 68 + am] = l;
            // store B split [k][n]
            float4 hv, lv;
            SPLIT_TF32(x4a.x, hv.x, lv.x); SPLIT_TF32(x4a.y, hv.y, lv.y);
            SPLIT_TF32(x4a.z, hv.z, lv.z); SPLIT_TF32(x4a.w, hv.w, lv.w);
            *(float4*)&Bh[bk * 136 + bsq * 4] = hv;
            *(float4*)&Bl[bk * 136 + bsq * 4] = lv;
            SPLIT_TF32(x4b.x, hv.x, lv.x); SPLIT_TF32(x4b.y, hv.y, lv.y);
            SPLIT_TF32(x4b.z, hv.z, lv.z); SPLIT_TF32(x4b.w, hv.w, lv.w);
            *(float4*)&Bh[(bk + 8) * 136 + bsq * 4] = hv;
            *(float4*)&Bl[(bk + 8) * 136 + bsq * 4] = lv;
        }
        __syncthreads();

        if (k0 + 16 < KDIM) {   // prefetch next chunk (hidden under compute)
            w4  = *(const float4*)(Wp + (size_t)am * KDIM + k0 + 16 + akq * 4);
            x4a = *(const float4*)(Xp + (size_t)(k0 + 16 + bk) * S_ + bsq * 4);
            x4b = *(const float4*)(Xp + (size_t)(k0 + 16 + bk + 8) * S_ + bsq * 4);
        }

#pragma unroll
        for (int kk = 0; kk < 2; kk++) {
            const int k8 = kk * 8;
            uint32_t ah[2][4], al[2][4];
#pragma unroll
            for (int mt = 0; mt < 2; mt++) {
                int r = mbase + mt * 16 + g;
                ah[mt][0] = __float_as_uint(Ah[(k8 + tg) * 68 + r]);
                ah[mt][1] = __float_as_uint(Ah[(k8 + tg) * 68 + r + 8]);
                ah[mt][2] = __float_as_uint(Ah[(k8 + tg + 4) * 68 + r]);
                ah[mt][3] = __float_as_uint(Ah[(k8 + tg + 4) * 68 + r + 8]);
                al[mt][0] = __float_as_uint(Al[(k8 + tg) * 68 + r]);
                al[mt][1] = __float_as_uint(Al[(k8 + tg) * 68 + r + 8]);
                al[mt][2] = __float_as_uint(Al[(k8 + tg + 4) * 68 + r]);
                al[mt][3] = __float_as_uint(Al[(k8 + tg + 4) * 68 + r + 8]);
            }
            uint32_t bh[4][2], bl[4][2];
#pragma unroll
            for (int nt = 0; nt < 4; nt++) {
                int n = nbase + nt * 8 + g;
                bh[nt][0] = __float_as_uint(Bh[(k8 + tg) * 136 + n]);
                bh[nt][1] = __float_as_uint(Bh[(k8 + tg + 4) * 136 + n]);
                bl[nt][0] = __float_as_uint(Bl[(k8 + tg) * 136 + n]);
                bl[nt][1] = __float_as_uint(Bl[(k8 + tg + 4) * 136 + n]);
            }
#pragma unroll
            for (int mt = 0; mt < 2; mt++)
#pragma unroll
                for (int nt = 0; nt < 4; nt++) {
                    mma_tf32(acc[mt][nt], ah[mt][0], ah[mt][1], ah[mt][2], ah[mt][3], bh[nt][0], bh[nt][1]);
                    mma_tf32(acc[mt][nt], ah[mt][0], ah[mt][1], ah[mt][2], ah[mt][3], bl[nt][0], bl[nt][1]);
                    mma_tf32(acc[mt][nt], al[mt][0], al[mt][1], al[mt][2], al[mt][3], bh[nt][0], bh[nt][1]);
                }
        }
    }

    float* Cp = C + ((size_t)b * Mtot + o0) * S_ + s0;
#pragma unroll
    for (int mt = 0; mt < 2; mt++)
#pragma unroll
        for (int rh = 0; rh < 2; rh++) {
            int row = mbase + mt * 16 + rh * 8 + g;
            float bv = BIAS ? bias[o0 + row] : 0.f;
#pragma unroll
            for (int nt = 0; nt < 4; nt++) {
                int col = nbase + nt * 8 + tg * 2;
                float2 v2 = make_float2(acc[mt][nt][rh * 2 + 0] + bv,
                                        acc[mt][nt][rh * 2 + 1] + bv);
                *(float2*)(Cp + (size_t)row * S_ + col) = v2;
            }
        }
}

// ---------------------------------------------------------------------------
// 2a) RoPE (in place)
// ---------------------------------------------------------------------------
__global__ __launch_bounds__(256) void rope_kernel(float* __restrict__ qkv)
{
    int gid = blockIdx.x * blockDim.x + threadIdx.x;
    int s  = gid & 1023;
    int r  = gid >> 10;
    int h  = r & 7;
    int b  = (r >> 3) & 7;
    int qk = r >> 6;

    float* p = qkv + ((size_t)b * O1_ + qk * HID_ + h * D_) * S_ + s;
    const float* sp = &g_sin[s * 16];
    const float* cp = &g_cos[s * 16];
#pragma unroll
    for (int d = 0; d < 16; d++) {
        float c  = cp[d];
        float sn = sp[d];
        float x = p[(size_t)d * S_];
        float y = p[(size_t)(d + 16) * S_];
        p[(size_t)d * S_]        = x * c - y * sn;
        p[(size_t)(d + 16) * S_] = y * c + x * sn;
    }
}

// ---------------------------------------------------------------------------
// 2b) L2 norm over the sequence axis (per q,k channel row)
// ---------------------------------------------------------------------------
__global__ __launch_bounds__(256) void l2norm_kernel(float* __restrict__ qkv)
{
    int row = blockIdx.x;
    int b = row >> 10;
    int o = row & 1023;
    float* p = qkv + ((size_t)b * O1_ + o) * S_;

    int tid = threadIdx.x;
    float4 v = *(float4*)(p + tid * 4);
    float ss = v.x * v.x + v.y * v.y + v.z * v.z + v.w * v.w;
#pragma unroll
    for (int off = 16; off; off >>= 1)
        ss += __shfl_xor_sync(0xffffffffu, ss, off);

    __shared__ float wss[8];
    if ((tid & 31) == 0) wss[tid >> 5] = ss;
    __syncthreads();
    if (tid < 32) {
        float t = (tid < 8) ? wss[tid] : 0.f;
#pragma unroll
        for (int off = 4; off; off >>= 1)
            t += __shfl_xor_sync(0xffffffffu, t, off);
        if (tid == 0) wss[0] = t;
    }
    __syncthreads();

    float inv = 1.0f / fmaxf(sqrtf(wss[0]), 1e-12f);
    v.x *= inv; v.y *= inv; v.z *= inv; v.w *= inv;
    *(float4*)(p + tid * 4) = v;
}

// ---------------------------------------------------------------------------
// 3) Attention (tf32 tensor-core), i=64 x j-iter=128, 8 warps.
//    Ks stride 136 (conflict-free S-phase B reads, row idx = tg),
//    Vs stride 132 (conflict-free O-phase B reads, row idx = g),
//    Qs/Ps stride 68 (conflict-free both phases).
// ---------------------------------------------------------------------------
#define AT_QS 0          // 64*68   = 4352
#define AT_KS 4352       // 64*136  = 8704
#define AT_VS 13056      // 64*132  = 8448
#define AT_PS 21504      // 128*68  = 8704
#define AT_L  30208      // 64
#define AT_SMEM_FLOATS 30272

__global__ __launch_bounds__(256) void attn_tc_kernel(
    const float* __restrict__ qkv, float* __restrict__ att)
{
    extern __shared__ float sm[];
    float* Qs  = sm + AT_QS;
    float* Ks  = sm + AT_KS;
    float* Vs  = sm + AT_VS;
    float* Ps  = sm + AT_PS;
    float* Lsm = sm + AT_L;

    const int tid  = threadIdx.x;
    const int lane = tid & 31;
    const int warp = tid >> 5;
    const int g  = lane >> 2;
    const int tg = lane & 3;
    const int wi = warp & 1;
    const int wq = warp >> 1;
    const int ib = wi * 32;

    const int i0 = blockIdx.x * 64;
    const int h  = blockIdx.y;
    const int b  = blockIdx.z;

    const float* Qg = qkv + ((size_t)b * O1_ + h * D_) * S_;
    const float* Kg = Qg + (size_t)HID_ * S_;
    const float* Vg = Qg + (size_t)(2 * HID_) * S_;

    for (int v = tid; v < 1024; v += 256) {
        int d = v >> 4, iq = v & 15;
        *(float4*)&Qs[d * 68 + iq * 4] =
            *(const float4*)(Qg + (size_t)d * S_ + i0 + iq * 4);
    }
    if (tid < 64) Lsm[tid] = 0.f;

    float oacc[2][2][4] = {};
    float l_acc[2][2]   = {};

    for (int j0 = 0; j0 < S_; j0 += 128) {
        __syncthreads();
        for (int v = tid; v < 2048; v += 256) {
            int d = v >> 5, jq = v & 31;
            *(float4*)&Ks[d * 136 + jq * 4] =
                *(const float4*)(Kg + (size_t)d * S_ + j0 + jq * 4);
            *(float4*)&Vs[d * 132 + jq * 4] =
                *(const float4*)(Vg + (size_t)d * S_ + j0 + jq * 4);
        }
        __syncthreads();

        const int jb = wq * 32;
        float sacc[2][4][4] = {};
#pragma unroll
        for (int kk = 0; kk < 8; kk++) {
            const int k0 = kk * 8;
            uint32_t a[2][4];
#pragma unroll
            for (int mt = 0; mt < 2; mt++) {
                int r = ib + mt * 16 + g;
                a[mt][0] = __float_as_uint(Qs[(k0 + tg) * 68 + r]);
                a[mt][1] = __float_as_uint(Qs[(k0 + tg) * 68 + r + 8]);
                a[mt][2] = __float_as_uint(Qs[(k0 + tg + 4) * 68 + r]);
                a[mt][3] = __float_as_uint(Qs[(k0 + tg + 4) * 68 + r + 8]);
            }
            uint32_t bb[4][2];
#pragma unroll
            for (int nt = 0; nt < 4; nt++) {
                int jc = jb + nt * 8 + g;
                bb[nt][0] = __float_as_uint(Ks[(k0 + tg) * 136 + jc]);
                bb[nt][1] = __float_as_uint(Ks[(k0 + tg + 4) * 136 + jc]);
            }
#pragma unroll
            for (int mt = 0; mt < 2; mt++)
#pragma unroll
                for (int nt = 0; nt < 4; nt++)
                    mma_tf32(sacc[mt][nt], a[mt][0], a[mt][1], a[mt][2], a[mt][3],
                             bb[nt][0], bb[nt][1]);
        }

#pragma unroll
        for (int mt = 0; mt < 2; mt++)
#pragma unroll
            for (int nt = 0; nt < 4; nt++)
#pragma unroll
                for (int c = 0; c < 4; c++) {
                    float p = __expf(10.f * sacc[mt][nt][c]);
                    int row = ib + mt * 16 + g + ((c >> 1) << 3);
                    int col = jb + nt * 8 + tg * 2 + (c & 1);
                    l_acc[mt][c >> 1] += p;
                    Ps[col * 68 + row] = p;
                }
        __syncthreads();

        const int db = wq * 16;
#pragma unroll
        for (int kk = 0; kk < 16; kk++) {
            const int k0 = kk * 8;
            uint32_t a[2][4];
#pragma unroll
            for (int mt = 0; mt < 2; mt++) {
                int r = ib + mt * 16 + g;
                a[mt][0] = __float_as_uint(Ps[(k0 + tg) * 68 + r]);
                a[mt][1] = __float_as_uint(Ps[(k0 + tg) * 68 + r + 8]);
                a[mt][2] = __float_as_uint(Ps[(k0 + tg + 4) * 68 + r]);
                a[mt][3] = __float_as_uint(Ps[(k0 + tg + 4) * 68 + r + 8]);
            }
            uint32_t bb[2][2];
#pragma unroll
            for (int nt = 0; nt < 2; nt++) {
                int dc = db + nt * 8 + g;
                bb[nt][0] = __float_as_uint(Vs[dc * 132 + k0 + tg]);
                bb[nt][1] = __float_as_uint(Vs[dc * 132 + k0 + tg + 4]);
            }
#pragma unroll
            for (int mt = 0; mt < 2; mt++)
#pragma unroll
                for (int nt = 0; nt < 2; nt++)
                    mma_tf32(oacc[mt][nt], a[mt][0], a[mt][1], a[mt][2], a[mt][3],
                             bb[nt][0], bb[nt][1]);
        }
    }

#pragma unroll
    for (int mt = 0; mt < 2; mt++)
#pragma unroll
        for (int rh = 0; rh < 2; rh++) {
            float l = l_acc[mt][rh];
            l += __shfl_xor_sync(0xffffffffu, l, 1);
            l += __shfl_xor_sync(0xffffffffu, l, 2);
            if (tg == 0)
                atomicAdd(&Lsm[ib + mt * 16 + rh * 8 + g], l);
        }
    __syncthreads();

    const int db = wq * 16;
#pragma unroll
    for (int mt = 0; mt < 2; mt++) {
        float inv0 = 1.0f / Lsm[ib + mt * 16 + g];
        float inv1 = 1.0f / Lsm[ib + mt * 16 + 8 + g];
#pragma unroll
        for (int nt = 0; nt < 2; nt++)
#pragma unroll
            for (int c = 0; c < 4; c++) {
                float o = oacc[mt][nt][c] * ((c >> 1) ? inv1 : inv0);
                int row = ib + mt * 16 + g + ((c >> 1) << 3);
                int col = db + nt * 8 + tg * 2 + (c & 1);
                Qs[col * 68 + row] = o;
            }
    }
    __syncthreads();

    float* Ap = att + ((size_t)b * HID_ + h * D_) * S_ + i0;
    for (int v = tid; v < 1024; v += 256) {
        int d = v >> 4, iq = v & 15;
        *(float4*)(Ap + (size_t)d * S_ + iq * 4) = *(float4*)&Qs[d * 68 + iq * 4];
    }
}

// ---------------------------------------------------------------------------
// Launch
// ---------------------------------------------------------------------------
extern "C" void kernel_launch(void* const* d_in, const int* in_sizes, int n_in,
                              void* d_out, int out_size)
{
    const float* x     = (const float*)d_in[0];
    const float* w_qkv = (const float*)d_in[1];
    const float* w_out = (const float*)d_in[2];
    const float* b_out = (const float*)d_in[3];
    float* out = (float*)d_out;

    float* qkv; cudaGetSymbolAddress((void**)&qkv, g_qkv);
    float* att; cudaGetSymbolAddress((void**)&att, g_att);

    static const size_t attn_smem = AT_SMEM_FLOATS * sizeof(float);  // ~118 KB
    cudaFuncSetAttribute(attn_tc_kernel,
                         cudaFuncAttributeMaxDynamicSharedMemorySize,
                         (int)attn_smem);

    init_tab_kernel<<<(S_ * 16 + 255) / 256, 256>>>();

    {   // QKV projection (split-tf32, fp32-accurate)
        dim3 grid(S_ / 128, O1_ / 64, B_);
        gemm_tc_kernel<256, false><<<grid, 256>>>(w_qkv, x, nullptr, qkv, O1_);
    }

    rope_kernel<<<(2 * B_ * H_ * S_) / 256, 256>>>(qkv);
    l2norm_kernel<<<B_ * 2 * HID_, 256>>>(qkv);

    {   // Attention
        dim3 grid(S_ / 64, H_, B_);
        attn_tc_kernel<<<grid, 256, attn_smem>>>(qkv, att);
    }

    {   // Output projection (split-tf32 + bias)
        dim3 grid(S_ / 128, C_ / 64, B_);
        gemm_tc_kernel<512, true><<<grid, 256>>>(w_out, att, b_out, out, C_);
    }
}

// round 9
// speedup vs baseline: 2.3702x; 1.2594x over previous
#include <cuda_runtime.h>
#include <math.h>
#include <stdint.h>

// ---------------------------------------------------------------------------
// Problem constants
//   x: (8, 256, 32, 32)  -> [b][c][s], s = 1024
//   w_qkv: (1536, 256), w_out: (256, 512), b_out: (256,)
//   HEADS=8, DIM_HEAD=64, SCALE=10, ROT_DIM=32 (16 freqs)
//   L2 norm is over the SEQUENCE axis (per (b,h,d) row), per reference.
// ---------------------------------------------------------------------------
#define B_   8
#define C_   256
#define S_   1024
#define H_   8
#define D_   64
#define HID_ 512
#define O1_  1536

__device__ float g_qkv[B_ * O1_ * S_];     // [b][o][s]
__device__ float g_att[B_ * HID_ * S_];    // [b][h*64+d][s]
__device__ float g_sin[S_ * 16];
__device__ float g_cos[S_ * 16];

// ---------------------------------------------------------------------------
// m16n8k8 tf32 MMA + helpers
// ---------------------------------------------------------------------------
__device__ __forceinline__ void mma_tf32(float c[4],
    uint32_t a0, uint32_t a1, uint32_t a2, uint32_t a3,
    uint32_t b0, uint32_t b1)
{
    asm volatile(
        "mma.sync.aligned.m16n8k8.row.col.f32.tf32.tf32.f32 "
        "{%0,%1,%2,%3}, {%4,%5,%6,%7}, {%8,%9}, {%0,%1,%2,%3};"
        : "+f"(c[0]), "+f"(c[1]), "+f"(c[2]), "+f"(c[3])
        : "r"(a0), "r"(a1), "r"(a2), "r"(a3), "r"(b0), "r"(b1));
}

#define SPLIT_TF32(v, H, L) do { uint32_t u_;                         \
    asm("cvt.rna.tf32.f32 %0, %1;" : "=r"(u_) : "f"(v));              \
    (H) = __uint_as_float(u_); (L) = (v) - (H); } while (0)

__device__ __forceinline__ void cp_async16(uint32_t s, const void* g) {
    asm volatile("cp.async.cg.shared.global [%0], [%1], 16;" :: "r"(s), "l"(g));
}
#define CP_COMMIT() asm volatile("cp.async.commit_group;")
#define CP_WAIT1()  asm volatile("cp.async.wait_group 1;")
#define CP_WAIT0()  asm volatile("cp.async.wait_group 0;")

// ---------------------------------------------------------------------------
// 0) sin/cos table
// ---------------------------------------------------------------------------
__global__ void init_tab_kernel() {
    int id = blockIdx.x * blockDim.x + threadIdx.x;
    if (id >= S_ * 16) return;
    int s = id >> 4;
    int j = id & 15;
    float invf = (float)pow(10000.0, -(double)j / 16.0);
    double ang = (double)s * (double)invf;
    g_sin[id] = (float)sin(ang);
    g_cos[id] = (float)cos(ang);
}

// ---------------------------------------------------------------------------
// 1+4) Split-tf32 tensor-core GEMM (fp32-accurate via 3 MMAs)
//      A smem stride 72 (8tg+g banks, conflict-free frag reads)
// ---------------------------------------------------------------------------
template<int KDIM, bool BIAS>
__global__ __launch_bounds__(256) void gemm_tc_kernel(
    const float* __restrict__ W, const float* __restrict__ X,
    const float* __restrict__ bias, float* __restrict__ C, int Mtot)
{
    __shared__ float Ah[16 * 72], Al[16 * 72];
    __shared__ float Bh[16 * 136], Bl[16 * 136];

    const int tid  = threadIdx.x;
    const int lane = tid & 31, warp = tid >> 5;
    const int g = lane >> 2, tg = lane & 3;
    const int wm = warp & 1, wn = warp >> 1;
    const int mbase = wm * 32, nbase = wn * 32;

    const int s0 = blockIdx.x * 128;
    const int o0 = blockIdx.y * 64;
    const int b  = blockIdx.z;

    const float* Wp = W + (size_t)o0 * KDIM;
    const float* Xp = X + (size_t)b * KDIM * S_ + s0;

    const int am = tid >> 2, akq = tid & 3;
    const int bk = tid >> 5, bsq = tid & 31;

    float4 w4  = *(const float4*)(Wp + (size_t)am * KDIM + akq * 4);
    float4 x4a = *(const float4*)(Xp + (size_t)bk * S_ + bsq * 4);
    float4 x4b = *(const float4*)(Xp + (size_t)(bk + 8) * S_ + bsq * 4);

    float acc[2][4][4] = {};

    for (int k0 = 0; k0 < KDIM; k0 += 16) {
        __syncthreads();
        {
            float h, l;
            SPLIT_TF32(w4.x, h, l); Ah[(akq * 4 + 0) * 72 + am] = h; Al[(akq * 4 + 0) * 72 + am] = l;
            SPLIT_TF32(w4.y, h, l); Ah[(akq * 4 + 1) * 72 + am] = h; Al[(akq * 4 + 1) * 72 + am] = l;
            SPLIT_TF32(w4.z, h, l); Ah[(akq * 4 + 2) * 72 + am] = h; Al[(akq * 4 + 2) * 72 + am] = l;
            SPLIT_TF32(w4.w, h, l); Ah[(akq * 4 + 3) * 72 + am] = h; Al[(akq * 4 + 3) * 72 + am] = l;
            float4 hv, lv;
            SPLIT_TF32(x4a.x, hv.x, lv.x); SPLIT_TF32(x4a.y, hv.y, lv.y);
            SPLIT_TF32(x4a.z, hv.z, lv.z); SPLIT_TF32(x4a.w, hv.w, lv.w);
            *(float4*)&Bh[bk * 136 + bsq * 4] = hv;
            *(float4*)&Bl[bk * 136 + bsq * 4] = lv;
            SPLIT_TF32(x4b.x, hv.x, lv.x); SPLIT_TF32(x4b.y, hv.y, lv.y);
            SPLIT_TF32(x4b.z, hv.z, lv.z); SPLIT_TF32(x4b.w, hv.w, lv.w);
            *(float4*)&Bh[(bk + 8) * 136 + bsq * 4] = hv;
            *(float4*)&Bl[(bk + 8) * 136 + bsq * 4] = lv;
        }
        __syncthreads();

        if (k0 + 16 < KDIM) {
            w4  = *(const float4*)(Wp + (size_t)am * KDIM + k0 + 16 + akq * 4);
            x4a = *(const float4*)(Xp + (size_t)(k0 + 16 + bk) * S_ + bsq * 4);
            x4b = *(const float4*)(Xp + (size_t)(k0 + 16 + bk + 8) * S_ + bsq * 4);
        }

#pragma unroll
        for (int kk = 0; kk < 2; kk++) {
            const int k8 = kk * 8;
            uint32_t ah[2][4], al[2][4];
#pragma unroll
            for (int mt = 0; mt < 2; mt++) {
                int r = mbase + mt * 16 + g;
                ah[mt][0] = __float_as_uint(Ah[(k8 + tg) * 72 + r]);
                ah[mt][1] = __float_as_uint(Ah[(k8 + tg) * 72 + r + 8]);
                ah[mt][2] = __float_as_uint(Ah[(k8 + tg + 4) * 72 + r]);
                ah[mt][3] = __float_as_uint(Ah[(k8 + tg + 4) * 72 + r + 8]);
                al[mt][0] = __float_as_uint(Al[(k8 + tg) * 72 + r]);
                al[mt][1] = __float_as_uint(Al[(k8 + tg) * 72 + r + 8]);
                al[mt][2] = __float_as_uint(Al[(k8 + tg + 4) * 72 + r]);
                al[mt][3] = __float_as_uint(Al[(k8 + tg + 4) * 72 + r + 8]);
            }
            uint32_t bh[4][2], bl[4][2];
#pragma unroll
            for (int nt = 0; nt < 4; nt++) {
                int n = nbase + nt * 8 + g;
                bh[nt][0] = __float_as_uint(Bh[(k8 + tg) * 136 + n]);
                bh[nt][1] = __float_as_uint(Bh[(k8 + tg + 4) * 136 + n]);
                bl[nt][0] = __float_as_uint(Bl[(k8 + tg) * 136 + n]);
                bl[nt][1] = __float_as_uint(Bl[(k8 + tg + 4) * 136 + n]);
            }
#pragma unroll
            for (int mt = 0; mt < 2; mt++)
#pragma unroll
                for (int nt = 0; nt < 4; nt++) {
                    mma_tf32(acc[mt][nt], ah[mt][0], ah[mt][1], ah[mt][2], ah[mt][3], bh[nt][0], bh[nt][1]);
                    mma_tf32(acc[mt][nt], ah[mt][0], ah[mt][1], ah[mt][2], ah[mt][3], bl[nt][0], bl[nt][1]);
                    mma_tf32(acc[mt][nt], al[mt][0], al[mt][1], al[mt][2], al[mt][3], bh[nt][0], bh[nt][1]);
                }
        }
    }

    float* Cp = C + ((size_t)b * Mtot + o0) * S_ + s0;
#pragma unroll
    for (int mt = 0; mt < 2; mt++)
#pragma unroll
        for (int rh = 0; rh < 2; rh++) {
            int row = mbase + mt * 16 + rh * 8 + g;
            float bv = BIAS ? bias[o0 + row] : 0.f;
#pragma unroll
            for (int nt = 0; nt < 4; nt++) {
                int col = nbase + nt * 8 + tg * 2;
                float2 v2 = make_float2(acc[mt][nt][rh * 2 + 0] + bv,
                                        acc[mt][nt][rh * 2 + 1] + bv);
                *(float2*)(Cp + (size_t)row * S_ + col) = v2;
            }
        }
}

// ---------------------------------------------------------------------------
// 2a) RoPE (in place)
// ---------------------------------------------------------------------------
__global__ __launch_bounds__(256) void rope_kernel(float* __restrict__ qkv)
{
    int gid = blockIdx.x * blockDim.x + threadIdx.x;
    int s  = gid & 1023;
    int r  = gid >> 10;
    int h  = r & 7;
    int b  = (r >> 3) & 7;
    int qk = r >> 6;

    float* p = qkv + ((size_t)b * O1_ + qk * HID_ + h * D_) * S_ + s;
    const float* sp = &g_sin[s * 16];
    const float* cp = &g_cos[s * 16];
#pragma unroll
    for (int d = 0; d < 16; d++) {
        float c  = cp[d];
        float sn = sp[d];
        float x = p[(size_t)d * S_];
        float y = p[(size_t)(d + 16) * S_];
        p[(size_t)d * S_]        = x * c - y * sn;
        p[(size_t)(d + 16) * S_] = y * c + x * sn;
    }
}

// ---------------------------------------------------------------------------
// 2b) L2 norm over the sequence axis
// ---------------------------------------------------------------------------
__global__ __launch_bounds__(256) void l2norm_kernel(float* __restrict__ qkv)
{
    int row = blockIdx.x;
    int b = row >> 10;
    int o = row & 1023;
    float* p = qkv + ((size_t)b * O1_ + o) * S_;

    int tid = threadIdx.x;
    float4 v = *(float4*)(p + tid * 4);
    float ss = v.x * v.x + v.y * v.y + v.z * v.z + v.w * v.w;
#pragma unroll
    for (int off = 16; off; off >>= 1)
        ss += __shfl_xor_sync(0xffffffffu, ss, off);

    __shared__ float wss[8];
    if ((tid & 31) == 0) wss[tid >> 5] = ss;
    __syncthreads();
    if (tid < 32) {
        float t = (tid < 8) ? wss[tid] : 0.f;
#pragma unroll
        for (int off = 4; off; off >>= 1)
            t += __shfl_xor_sync(0xffffffffu, t, off);
        if (tid == 0) wss[0] = t;
    }
    __syncthreads();

    float inv = 1.0f / fmaxf(sqrtf(wss[0]), 1e-12f);
    v.x *= inv; v.y *= inv; v.z *= inv; v.w *= inv;
    *(float4*)(p + tid * 4) = v;
}

// ---------------------------------------------------------------------------
// 3) Attention, register-resident P + cp.async double buffering.
//    i-tile 64, j-iter 128, 8 warps (wi = i-half, wq = j-slice of 32).
//    S phase: K columns fed permuted (f(g)) so the exp'd accumulator IS the
//    A-fragment of the O mma (a = c0,c2,c1,c3). Each warp accumulates partial
//    O (its 32 j's) over all d=64 in registers; 4-round staged smem reduction
//    at the end.  Strides: Qs 72 (8tg+g), Ks 136 (8tg+f(g)), Vs 132 (4g+tg),
//    Ot 68 (8tg+g stores) — all conflict-free.
// ---------------------------------------------------------------------------
#define AT_QS 0            // 64*72  = 4608   (reused as Ot[d][i] stride 68)
#define AT_K0 4608         // 64*136 = 8704
#define AT_K1 13312
#define AT_V0 22016        // 64*132 = 8448
#define AT_V1 30464
#define AT_L  38912        // 64
#define AT_SMEM_FLOATS 38976

__global__ __launch_bounds__(256) void attn_tc_kernel(
    const float* __restrict__ qkv, float* __restrict__ att)
{
    extern __shared__ float sm[];
    float* Qs  = sm + AT_QS;
    float* Lsm = sm + AT_L;

    const int tid  = threadIdx.x;
    const int lane = tid & 31;
    const int warp = tid >> 5;
    const int g  = lane >> 2;
    const int tg = lane & 3;
    const int wi = warp & 1;
    const int wq = warp >> 1;
    const int ib = wi * 32;
    const int jb = wq * 32;
    const int fg = (g >> 1) | ((g & 1) << 2);   // K column permutation

    const int i0 = blockIdx.x * 64;
    const int h  = blockIdx.y;
    const int b  = blockIdx.z;

    const float* Qg = qkv + ((size_t)b * O1_ + h * D_) * S_;
    const float* Kg = Qg + (size_t)HID_ * S_;
    const float* Vg = Qg + (size_t)(2 * HID_) * S_;

    uint32_t smbase = (uint32_t)__cvta_generic_to_shared(sm);

    // Q tile [d][i], stride 72
    for (int v = tid; v < 1024; v += 256) {
        int d = v >> 4, iq = v & 15;
        *(float4*)&Qs[d * 72 + iq * 4] =
            *(const float4*)(Qg + (size_t)d * S_ + i0 + iq * 4);
    }
    if (tid < 64) Lsm[tid] = 0.f;

    // async K/V tile loaders (64 KB per iter)
    const int ld = tid >> 5, ljq = tid & 31;   // d rows: ld, ld+8, ... (8 per thread)
    auto issue_kv = [&](int buf, int j0) {
        uint32_t koff = (buf ? AT_K1 : AT_K0);
        uint32_t voff = (buf ? AT_V1 : AT_V0);
#pragma unroll
        for (int r = 0; r < 8; r++) {
            int d = ld + r * 8;
            cp_async16(smbase + (koff + d * 136 + ljq * 4) * 4,
                       Kg + (size_t)d * S_ + j0 + ljq * 4);
            cp_async16(smbase + (voff + d * 132 + ljq * 4) * 4,
                       Vg + (size_t)d * S_ + j0 + ljq * 4);
        }
    };

    issue_kv(0, 0);
    CP_COMMIT();

    float oacc[2][8][4] = {};
    float l_acc[2][2]   = {};

    for (int it = 0; it < 8; it++) {
        const int cur = it & 1;
        __syncthreads();                       // prev compute done with buf cur^1
        if (it + 1 < 8) {
            issue_kv(cur ^ 1, (it + 1) * 128);
            CP_COMMIT();
            CP_WAIT1();
        } else {
            CP_WAIT0();
        }
        __syncthreads();                       // buf cur data visible

        const float* Ks = sm + (cur ? AT_K1 : AT_K0);
        const float* Vs = sm + (cur ? AT_V1 : AT_V0);

        // ---- S phase: S[i 32][j 32] per warp, K columns permuted by fg
        float sacc[2][4][4] = {};
#pragma unroll
        for (int kk = 0; kk < 8; kk++) {
            const int k0 = kk * 8;
            uint32_t a[2][4];
#pragma unroll
            for (int mt = 0; mt < 2; mt++) {
                int r = ib + mt * 16 + g;
                a[mt][0] = __float_as_uint(Qs[(k0 + tg) * 72 + r]);
                a[mt][1] = __float_as_uint(Qs[(k0 + tg) * 72 + r + 8]);
                a[mt][2] = __float_as_uint(Qs[(k0 + tg + 4) * 72 + r]);
                a[mt][3] = __float_as_uint(Qs[(k0 + tg + 4) * 72 + r + 8]);
            }
            uint32_t bb[4][2];
#pragma unroll
            for (int nt = 0; nt < 4; nt++) {
                int jc = jb + nt * 8 + fg;
                bb[nt][0] = __float_as_uint(Ks[(k0 + tg) * 136 + jc]);
                bb[nt][1] = __float_as_uint(Ks[(k0 + tg + 4) * 136 + jc]);
            }
#pragma unroll
            for (int mt = 0; mt < 2; mt++)
#pragma unroll
                for (int nt = 0; nt < 4; nt++)
                    mma_tf32(sacc[mt][nt], a[mt][0], a[mt][1], a[mt][2], a[mt][3],
                             bb[nt][0], bb[nt][1]);
        }

        // ---- exp in place + row sums (permutation is j-bijection; sums OK)
#pragma unroll
        for (int mt = 0; mt < 2; mt++)
#pragma unroll
            for (int nt = 0; nt < 4; nt++) {
                float p0 = __expf(10.f * sacc[mt][nt][0]);
                float p1 = __expf(10.f * sacc[mt][nt][1]);
                float p2 = __expf(10.f * sacc[mt][nt][2]);
                float p3 = __expf(10.f * sacc[mt][nt][3]);
                sacc[mt][nt][0] = p0; sacc[mt][nt][1] = p1;
                sacc[mt][nt][2] = p2; sacc[mt][nt][3] = p3;
                l_acc[mt][0] += p0 + p1;      // row g
                l_acc[mt][1] += p2 + p3;      // row g+8
            }

        // ---- O phase: P (registers) x V^T, n = all 64 d, k = this warp's 32 j
#pragma unroll
        for (int ks = 0; ks < 4; ks++) {
            const int jk = jb + ks * 8;
            uint32_t bb[8][2];
#pragma unroll
            for (int nt = 0; nt < 8; nt++) {
                int dc = nt * 8 + g;
                bb[nt][0] = __float_as_uint(Vs[dc * 132 + jk + tg]);
                bb[nt][1] = __float_as_uint(Vs[dc * 132 + jk + tg + 4]);
            }
#pragma unroll
            for (int mt = 0; mt < 2; mt++) {
                uint32_t a0 = __float_as_uint(sacc[mt][ks][0]);
                uint32_t a1 = __float_as_uint(sacc[mt][ks][2]);
                uint32_t a2 = __float_as_uint(sacc[mt][ks][1]);
                uint32_t a3 = __float_as_uint(sacc[mt][ks][3]);
#pragma unroll
                for (int nt = 0; nt < 8; nt++)
                    mma_tf32(oacc[mt][nt], a0, a1, a2, a3, bb[nt][0], bb[nt][1]);
            }
        }
    }

    // ---- row sums: reduce over tg lanes, merge 4 j-warps via atomicAdd
#pragma unroll
    for (int mt = 0; mt < 2; mt++)
#pragma unroll
        for (int rh = 0; rh < 2; rh++) {
            float l = l_acc[mt][rh];
            l += __shfl_xor_sync(0xffffffffu, l, 1);
            l += __shfl_xor_sync(0xffffffffu, l, 2);
            if (tg == 0)
                atomicAdd(&Lsm[ib + mt * 16 + rh * 8 + g], l);
        }
    __syncthreads();   // Q reads + Lsm adds complete; Qs reusable as Ot

    // ---- staged reduction of partial O across the 4 j-warps into Ot=Qs[d][i]
#pragma unroll
    for (int r = 0; r < 4; r++) {
        if (wq == r) {
#pragma unroll
            for (int mt = 0; mt < 2; mt++)
#pragma unroll
                for (int nt = 0; nt < 8; nt++)
#pragma unroll
                    for (int c = 0; c < 4; c++) {
                        int row = ib + mt * 16 + g + ((c >> 1) << 3);
                        int col = nt * 8 + tg * 2 + (c & 1);
                        if (r == 0) Qs[col * 68 + row] = oacc[mt][nt][c];
                        else        Qs[col * 68 + row] += oacc[mt][nt][c];
                    }
        }
        __syncthreads();
    }

    if (tid < 64) Lsm[tid] = 1.0f / Lsm[tid];
    __syncthreads();

    // ---- normalized, coalesced store [d][s]
    float* Ap = att + ((size_t)b * HID_ + h * D_) * S_ + i0;
    for (int v = tid; v < 1024; v += 256) {
        int d = v >> 4, iq = v & 15;
        float4 o = *(float4*)&Qs[d * 68 + iq * 4];
        o.x *= Lsm[iq * 4 + 0];
        o.y *= Lsm[iq * 4 + 1];
        o.z *= Lsm[iq * 4 + 2];
        o.w *= Lsm[iq * 4 + 3];
        *(float4*)(Ap + (size_t)d * S_ + iq * 4) = o;
    }
}

// ---------------------------------------------------------------------------
// Launch
// ---------------------------------------------------------------------------
extern "C" void kernel_launch(void* const* d_in, const int* in_sizes, int n_in,
                              void* d_out, int out_size)
{
    const float* x     = (const float*)d_in[0];
    const float* w_qkv = (const float*)d_in[1];
    const float* w_out = (const float*)d_in[2];
    const float* b_out = (const float*)d_in[3];
    float* out = (float*)d_out;

    float* qkv; cudaGetSymbolAddress((void**)&qkv, g_qkv);
    float* att; cudaGetSymbolAddress((void**)&att, g_att);

    static const size_t attn_smem = AT_SMEM_FLOATS * sizeof(float);  // ~152 KB
    cudaFuncSetAttribute(attn_tc_kernel,
                         cudaFuncAttributeMaxDynamicSharedMemorySize,
                         (int)attn_smem);

    init_tab_kernel<<<(S_ * 16 + 255) / 256, 256>>>();

    {   // QKV projection (split-tf32, fp32-accurate)
        dim3 grid(S_ / 128, O1_ / 64, B_);
        gemm_tc_kernel<256, false><<<grid, 256>>>(w_qkv, x, nullptr, qkv, O1_);
    }

    rope_kernel<<<(2 * B_ * H_ * S_) / 256, 256>>>(qkv);
    l2norm_kernel<<<B_ * 2 * HID_, 256>>>(qkv);

    {   // Attention
        dim3 grid(S_ / 64, H_, B_);
        attn_tc_kernel<<<grid, 256, attn_smem>>>(qkv, att);
    }

    {   // Output projection (split-tf32 + bias)
        dim3 grid(S_ / 128, C_ / 64, B_);
        gemm_tc_kernel<512, true><<<grid, 256>>>(w_out, att, b_out, out, C_);
    }
}

// round 10
// speedup vs baseline: 3.0068x; 1.2686x over previous
#include <cuda_runtime.h>
#include <cuda_bf16.h>
#include <math.h>
#include <stdint.h>

// ---------------------------------------------------------------------------
// Problem constants
//   x: (8, 256, 32, 32)  -> [b][c][s], s = 1024
//   w_qkv: (1536, 256), w_out: (256, 512), b_out: (256,)
//   HEADS=8, DIM_HEAD=64, SCALE=10, ROT_DIM=32 (16 freqs)
//   L2 norm over the SEQUENCE axis (per (b,h,d) row), per reference.
// ---------------------------------------------------------------------------
#define B_   8
#define C_   256
#define S_   1024
#define H_   8
#define D_   64
#define HID_ 512
#define O1_  1536

__device__ float g_qkv[B_ * O1_ * S_];     // [b][o][s]
__device__ float g_att[B_ * HID_ * S_];    // [b][h*64+d][s]
__device__ float g_sin[S_ * 16];
__device__ float g_cos[S_ * 16];

// ---------------------------------------------------------------------------
// MMA helpers
// ---------------------------------------------------------------------------
__device__ __forceinline__ void mma_tf32(float c[4],
    uint32_t a0, uint32_t a1, uint32_t a2, uint32_t a3,
    uint32_t b0, uint32_t b1)
{
    asm volatile(
        "mma.sync.aligned.m16n8k8.row.col.f32.tf32.tf32.f32 "
        "{%0,%1,%2,%3}, {%4,%5,%6,%7}, {%8,%9}, {%0,%1,%2,%3};"
        : "+f"(c[0]), "+f"(c[1]), "+f"(c[2]), "+f"(c[3])
        : "r"(a0), "r"(a1), "r"(a2), "r"(a3), "r"(b0), "r"(b1));
}

__device__ __forceinline__ void mma_bf16(float c[4],
    uint32_t a0, uint32_t a1, uint32_t a2, uint32_t a3,
    uint32_t b0, uint32_t b1)
{
    asm volatile(
        "mma.sync.aligned.m16n8k16.row.col.f32.bf16.bf16.f32 "
        "{%0,%1,%2,%3}, {%4,%5,%6,%7}, {%8,%9}, {%0,%1,%2,%3};"
        : "+f"(c[0]), "+f"(c[1]), "+f"(c[2]), "+f"(c[3])
        : "r"(a0), "r"(a1), "r"(a2), "r"(a3), "r"(b0), "r"(b1));
}

// pack two floats' bf16 hi/lo halves: returns (hi(k_even), hi(k_odd)) packed
__device__ __forceinline__ void split_pack_bf16(float v0, float v1,
                                                uint32_t& hp, uint32_t& lp)
{
    __nv_bfloat16 h0 = __float2bfloat16_rn(v0);
    __nv_bfloat16 h1 = __float2bfloat16_rn(v1);
    __nv_bfloat16 l0 = __float2bfloat16_rn(v0 - __bfloat162float(h0));
    __nv_bfloat16 l1 = __float2bfloat16_rn(v1 - __bfloat162float(h1));
    __nv_bfloat162 hv = __halves2bfloat162(h0, h1);
    __nv_bfloat162 lv = __halves2bfloat162(l0, l1);
    hp = *(uint32_t*)&hv;
    lp = *(uint32_t*)&lv;
}

__device__ __forceinline__ void cp_async16(uint32_t s, const void* g) {
    asm volatile("cp.async.cg.shared.global [%0], [%1], 16;" :: "r"(s), "l"(g));
}
#define CP_COMMIT() asm volatile("cp.async.commit_group;")
#define CP_WAIT1()  asm volatile("cp.async.wait_group 1;")
#define CP_WAIT0()  asm volatile("cp.async.wait_group 0;")

// ---------------------------------------------------------------------------
// 0) sin/cos table
// ---------------------------------------------------------------------------
__global__ void init_tab_kernel() {
    int id = blockIdx.x * blockDim.x + threadIdx.x;
    if (id >= S_ * 16) return;
    int s = id >> 4;
    int j = id & 15;
    float invf = (float)pow(10000.0, -(double)j / 16.0);
    double ang = (double)s * (double)invf;
    g_sin[id] = (float)sin(ang);
    g_cos[id] = (float)cos(ang);
}

// ---------------------------------------------------------------------------
// 1+4) bf16 3-term split GEMM (m16n8k16), fp32-accurate to ~1.5e-5.
//      C[b, o0+m, s0+n] = sum_k W[o0+m][k] * X[b][k][s0+n] (+bias) (+rope)
//      Block 64(m) x 128(n), 8 warps (2m x 4n), k-chunk 16 (= 8 kpairs).
//      smem (uint32 bf16x2): Ah/Al [8 kpair][m64] stride 72;
//                            Bh/Bl [8 kpair][n128] stride 136.
//      ROPE: when o0 < 1024 (q/k region) the tile is one head; pair (d,d+16)
//      lives in (acc[0], acc[1]) of the same wm=0 thread -> register rope.
// ---------------------------------------------------------------------------
template<int KDIM, bool BIAS, bool ROPE>
__global__ __launch_bounds__(256) void gemm_bf16_kernel(
    const float* __restrict__ W, const float* __restrict__ X,
    const float* __restrict__ bias, float* __restrict__ C, int Mtot)
{
    __shared__ uint32_t Ah[8 * 72], Al[8 * 72];
    __shared__ uint32_t Bh[8 * 136], Bl[8 * 136];

    const int tid  = threadIdx.x;
    const int lane = tid & 31, warp = tid >> 5;
    const int g = lane >> 2, tg = lane & 3;
    const int wm = warp & 1, wn = warp >> 1;
    const int mbase = wm * 32, nbase = wn * 32;

    const int s0 = blockIdx.x * 128;
    const int o0 = blockIdx.y * 64;
    const int b  = blockIdx.z;

    const float* Wp = W + (size_t)o0 * KDIM;
    const float* Xp = X + (size_t)b * KDIM * S_ + s0;

    const int am = tid >> 2, akq = tid & 3;   // A: m row, k quad (2 kpairs)
    const int bp = tid >> 5, bnq = tid & 31;  // B: kpair row, n quad

    float4 w4  = *(const float4*)(Wp + (size_t)am * KDIM + akq * 4);
    float4 x4a = *(const float4*)(Xp + (size_t)(2 * bp) * S_ + bnq * 4);
    float4 x4b = *(const float4*)(Xp + (size_t)(2 * bp + 1) * S_ + bnq * 4);

    float acc[2][4][4] = {};

    for (int k0 = 0; k0 < KDIM; k0 += 16) {
        __syncthreads();
        {   // A: w4 = k {4akq..4akq+3} -> kpairs 2akq (x,y), 2akq+1 (z,w)
            uint32_t hp, lp;
            split_pack_bf16(w4.x, w4.y, hp, lp);
            Ah[(2 * akq + 0) * 72 + am] = hp; Al[(2 * akq + 0) * 72 + am] = lp;
            split_pack_bf16(w4.z, w4.w, hp, lp);
            Ah[(2 * akq + 1) * 72 + am] = hp; Al[(2 * akq + 1) * 72 + am] = lp;
            // B: pair rows k=2bp (x4a) and k=2bp+1 (x4b) elementwise over n
            uint32_t h0, l0, h1, l1, h2, l2, h3, l3;
            split_pack_bf16(x4a.x, x4b.x, h0, l0);
            split_pack_bf16(x4a.y, x4b.y, h1, l1);
            split_pack_bf16(x4a.z, x4b.z, h2, l2);
            split_pack_bf16(x4a.w, x4b.w, h3, l3);
            *(uint4*)&Bh[bp * 136 + bnq * 4] = make_uint4(h0, h1, h2, h3);
            *(uint4*)&Bl[bp * 136 + bnq * 4] = make_uint4(l0, l1, l2, l3);
        }
        __syncthreads();

        if (k0 + 16 < KDIM) {
            w4  = *(const float4*)(Wp + (size_t)am * KDIM + k0 + 16 + akq * 4);
            x4a = *(const float4*)(Xp + (size_t)(k0 + 16 + 2 * bp) * S_ + bnq * 4);
            x4b = *(const float4*)(Xp + (size_t)(k0 + 16 + 2 * bp + 1) * S_ + bnq * 4);
        }

        // fragments: A kpairs tg / tg+4, B kpairs tg / tg+4
        uint32_t ah[2][4], al[2][4];
#pragma unroll
        for (int mt = 0; mt < 2; mt++) {
            int r = mbase + mt * 16 + g;
            ah[mt][0] = Ah[tg * 72 + r];
            ah[mt][1] = Ah[tg * 72 + r + 8];
            ah[mt][2] = Ah[(tg + 4) * 72 + r];
            ah[mt][3] = Ah[(tg + 4) * 72 + r + 8];
            al[mt][0] = Al[tg * 72 + r];
            al[mt][1] = Al[tg * 72 + r + 8];
            al[mt][2] = Al[(tg + 4) * 72 + r];
            al[mt][3] = Al[(tg + 4) * 72 + r + 8];
        }
        uint32_t bh[4][2], bl[4][2];
#pragma unroll
        for (int nt = 0; nt < 4; nt++) {
            int n = nbase + nt * 8 + g;
            bh[nt][0] = Bh[tg * 136 + n];
            bh[nt][1] = Bh[(tg + 4) * 136 + n];
            bl[nt][0] = Bl[tg * 136 + n];
            bl[nt][1] = Bl[(tg + 4) * 136 + n];
        }
#pragma unroll
        for (int mt = 0; mt < 2; mt++)
#pragma unroll
            for (int nt = 0; nt < 4; nt++) {
                mma_bf16(acc[mt][nt], ah[mt][0], ah[mt][1], ah[mt][2], ah[mt][3], bh[nt][0], bh[nt][1]);
                mma_bf16(acc[mt][nt], ah[mt][0], ah[mt][1], ah[mt][2], ah[mt][3], bl[nt][0], bl[nt][1]);
                mma_bf16(acc[mt][nt], al[mt][0], al[mt][1], al[mt][2], al[mt][3], bh[nt][0], bh[nt][1]);
            }
    }

    // ---- optional fused RoPE (q/k region only; pair (d, d+16) = (mt0, mt1))
    if (ROPE && o0 < 2 * HID_ && wm == 0) {
#pragma unroll
        for (int rh = 0; rh < 2; rh++) {
            int d = rh * 8 + g;           // freq index, 0..15
#pragma unroll
            for (int nt = 0; nt < 4; nt++)
#pragma unroll
                for (int cl = 0; cl < 2; cl++) {
                    int col = s0 + nbase + nt * 8 + tg * 2 + cl;
                    float cs = g_cos[col * 16 + d];
                    float sn = g_sin[col * 16 + d];
                    float x = acc[0][nt][rh * 2 + cl];
                    float y = acc[1][nt][rh * 2 + cl];
                    acc[0][nt][rh * 2 + cl] = x * cs - y * sn;
                    acc[1][nt][rh * 2 + cl] = y * cs + x * sn;
                }
        }
    }

    float* Cp = C + ((size_t)b * Mtot + o0) * S_ + s0;
#pragma unroll
    for (int mt = 0; mt < 2; mt++)
#pragma unroll
        for (int rh = 0; rh < 2; rh++) {
            int row = mbase + mt * 16 + rh * 8 + g;
            float bv = BIAS ? bias[o0 + row] : 0.f;
#pragma unroll
            for (int nt = 0; nt < 4; nt++) {
                int col = nbase + nt * 8 + tg * 2;
                float2 v2 = make_float2(acc[mt][nt][rh * 2 + 0] + bv,
                                        acc[mt][nt][rh * 2 + 1] + bv);
                *(float2*)(Cp + (size_t)row * S_ + col) = v2;
            }
        }
}

// ---------------------------------------------------------------------------
// 2b) L2 norm over the sequence axis (rope already fused into GEMM)
// ---------------------------------------------------------------------------
__global__ __launch_bounds__(256) void l2norm_kernel(float* __restrict__ qkv)
{
    int row = blockIdx.x;
    int b = row >> 10;
    int o = row & 1023;
    float* p = qkv + ((size_t)b * O1_ + o) * S_;

    int tid = threadIdx.x;
    float4 v = *(float4*)(p + tid * 4);
    float ss = v.x * v.x + v.y * v.y + v.z * v.z + v.w * v.w;
#pragma unroll
    for (int off = 16; off; off >>= 1)
        ss += __shfl_xor_sync(0xffffffffu, ss, off);

    __shared__ float wss[8];
    if ((tid & 31) == 0) wss[tid >> 5] = ss;
    __syncthreads();
    if (tid < 32) {
        float t = (tid < 8) ? wss[tid] : 0.f;
#pragma unroll
        for (int off = 4; off; off >>= 1)
            t += __shfl_xor_sync(0xffffffffu, t, off);
        if (tid == 0) wss[0] = t;
    }
    __syncthreads();

    float inv = 1.0f / fmaxf(sqrtf(wss[0]), 1e-12f);
    v.x *= inv; v.y *= inv; v.z *= inv; v.w *= inv;
    *(float4*)(p + tid * 4) = v;
}

// ---------------------------------------------------------------------------
// 3) Attention (unchanged from R9): tf32, register-resident P, cp.async
//    double-buffered K/V, staged O reduction.
// ---------------------------------------------------------------------------
#define AT_QS 0            // 64*72  = 4608   (reused as Ot[d][i] stride 68)
#define AT_K0 4608         // 64*136 = 8704
#define AT_K1 13312
#define AT_V0 22016        // 64*132 = 8448
#define AT_V1 30464
#define AT_L  38912        // 64
#define AT_SMEM_FLOATS 38976

__global__ __launch_bounds__(256) void attn_tc_kernel(
    const float* __restrict__ qkv, float* __restrict__ att)
{
    extern __shared__ float sm[];
    float* Qs  = sm + AT_QS;
    float* Lsm = sm + AT_L;

    const int tid  = threadIdx.x;
    const int lane = tid & 31;
    const int warp = tid >> 5;
    const int g  = lane >> 2;
    const int tg = lane & 3;
    const int wi = warp & 1;
    const int wq = warp >> 1;
    const int ib = wi * 32;
    const int jb = wq * 32;
    const int fg = (g >> 1) | ((g & 1) << 2);

    const int i0 = blockIdx.x * 64;
    const int h  = blockIdx.y;
    const int b  = blockIdx.z;

    const float* Qg = qkv + ((size_t)b * O1_ + h * D_) * S_;
    const float* Kg = Qg + (size_t)HID_ * S_;
    const float* Vg = Qg + (size_t)(2 * HID_) * S_;

    uint32_t smbase = (uint32_t)__cvta_generic_to_shared(sm);

    for (int v = tid; v < 1024; v += 256) {
        int d = v >> 4, iq = v & 15;
        *(float4*)&Qs[d * 72 + iq * 4] =
            *(const float4*)(Qg + (size_t)d * S_ + i0 + iq * 4);
    }
    if (tid < 64) Lsm[tid] = 0.f;

    const int ld = tid >> 5, ljq = tid & 31;
    auto issue_kv = [&](int buf, int j0) {
        uint32_t koff = (buf ? AT_K1 : AT_K0);
        uint32_t voff = (buf ? AT_V1 : AT_V0);
#pragma unroll
        for (int r = 0; r < 8; r++) {
            int d = ld + r * 8;
            cp_async16(smbase + (koff + d * 136 + ljq * 4) * 4,
                       Kg + (size_t)d * S_ + j0 + ljq * 4);
            cp_async16(smbase + (voff + d * 132 + ljq * 4) * 4,
                       Vg + (size_t)d * S_ + j0 + ljq * 4);
        }
    };

    issue_kv(0, 0);
    CP_COMMIT();

    float oacc[2][8][4] = {};
    float l_acc[2][2]   = {};

    for (int it = 0; it < 8; it++) {
        const int cur = it & 1;
        __syncthreads();
        if (it + 1 < 8) {
            issue_kv(cur ^ 1, (it + 1) * 128);
            CP_COMMIT();
            CP_WAIT1();
        } else {
            CP_WAIT0();
        }
        __syncthreads();

        const float* Ks = sm + (cur ? AT_K1 : AT_K0);
        const float* Vs = sm + (cur ? AT_V1 : AT_V0);

        float sacc[2][4][4] = {};
#pragma unroll
        for (int kk = 0; kk < 8; kk++) {
            const int k0 = kk * 8;
            uint32_t a[2][4];
#pragma unroll
            for (int mt = 0; mt < 2; mt++) {
                int r = ib + mt * 16 + g;
                a[mt][0] = __float_as_uint(Qs[(k0 + tg) * 72 + r]);
                a[mt][1] = __float_as_uint(Qs[(k0 + tg) * 72 + r + 8]);
                a[mt][2] = __float_as_uint(Qs[(k0 + tg + 4) * 72 + r]);
                a[mt][3] = __float_as_uint(Qs[(k0 + tg + 4) * 72 + r + 8]);
            }
            uint32_t bb[4][2];
#pragma unroll
            for (int nt = 0; nt < 4; nt++) {
                int jc = jb + nt * 8 + fg;
                bb[nt][0] = __float_as_uint(Ks[(k0 + tg) * 136 + jc]);
                bb[nt][1] = __float_as_uint(Ks[(k0 + tg + 4) * 136 + jc]);
            }
#pragma unroll
            for (int mt = 0; mt < 2; mt++)
#pragma unroll
                for (int nt = 0; nt < 4; nt++)
                    mma_tf32(sacc[mt][nt], a[mt][0], a[mt][1], a[mt][2], a[mt][3],
                             bb[nt][0], bb[nt][1]);
        }

#pragma unroll
        for (int mt = 0; mt < 2; mt++)
#pragma unroll
            for (int nt = 0; nt < 4; nt++) {
                float p0 = __expf(10.f * sacc[mt][nt][0]);
                float p1 = __expf(10.f * sacc[mt][nt][1]);
                float p2 = __expf(10.f * sacc[mt][nt][2]);
                float p3 = __expf(10.f * sacc[mt][nt][3]);
                sacc[mt][nt][0] = p0; sacc[mt][nt][1] = p1;
                sacc[mt][nt][2] = p2; sacc[mt][nt][3] = p3;
                l_acc[mt][0] += p0 + p1;
                l_acc[mt][1] += p2 + p3;
            }

#pragma unroll
        for (int ks = 0; ks < 4; ks++) {
            const int jk = jb + ks * 8;
            uint32_t bb[8][2];
#pragma unroll
            for (int nt = 0; nt < 8; nt++) {
                int dc = nt * 8 + g;
                bb[nt][0] = __float_as_uint(Vs[dc * 132 + jk + tg]);
                bb[nt][1] = __float_as_uint(Vs[dc * 132 + jk + tg + 4]);
            }
#pragma unroll
            for (int mt = 0; mt < 2; mt++) {
                uint32_t a0 = __float_as_uint(sacc[mt][ks][0]);
                uint32_t a1 = __float_as_uint(sacc[mt][ks][2]);
                uint32_t a2 = __float_as_uint(sacc[mt][ks][1]);
                uint32_t a3 = __float_as_uint(sacc[mt][ks][3]);
#pragma unroll
                for (int nt = 0; nt < 8; nt++)
                    mma_tf32(oacc[mt][nt], a0, a1, a2, a3, bb[nt][0], bb[nt][1]);
            }
        }
    }

#pragma unroll
    for (int mt = 0; mt < 2; mt++)
#pragma unroll
        for (int rh = 0; rh < 2; rh++) {
            float l = l_acc[mt][rh];
            l += __shfl_xor_sync(0xffffffffu, l, 1);
            l += __shfl_xor_sync(0xffffffffu, l, 2);
            if (tg == 0)
                atomicAdd(&Lsm[ib + mt * 16 + rh * 8 + g], l);
        }
    __syncthreads();

#pragma unroll
    for (int r = 0; r < 4; r++) {
        if (wq == r) {
#pragma unroll
            for (int mt = 0; mt < 2; mt++)
#pragma unroll
                for (int nt = 0; nt < 8; nt++)
#pragma unroll
                    for (int c = 0; c < 4; c++) {
                        int row = ib + mt * 16 + g + ((c >> 1) << 3);
                        int col = nt * 8 + tg * 2 + (c & 1);
                        if (r == 0) Qs[col * 68 + row] = oacc[mt][nt][c];
                        else        Qs[col * 68 + row] += oacc[mt][nt][c];
                    }
        }
        __syncthreads();
    }

    if (tid < 64) Lsm[tid] = 1.0f / Lsm[tid];
    __syncthreads();

    float* Ap = att + ((size_t)b * HID_ + h * D_) * S_ + i0;
    for (int v = tid; v < 1024; v += 256) {
        int d = v >> 4, iq = v & 15;
        float4 o = *(float4*)&Qs[d * 68 + iq * 4];
        o.x *= Lsm[iq * 4 + 0];
        o.y *= Lsm[iq * 4 + 1];
        o.z *= Lsm[iq * 4 + 2];
        o.w *= Lsm[iq * 4 + 3];
        *(float4*)(Ap + (size_t)d * S_ + iq * 4) = o;
    }
}

// ---------------------------------------------------------------------------
// Launch
// ---------------------------------------------------------------------------
extern "C" void kernel_launch(void* const* d_in, const int* in_sizes, int n_in,
                              void* d_out, int out_size)
{
    const float* x     = (const float*)d_in[0];
    const float* w_qkv = (const float*)d_in[1];
    const float* w_out = (const float*)d_in[2];
    const float* b_out = (const float*)d_in[3];
    float* out = (float*)d_out;

    float* qkv; cudaGetSymbolAddress((void**)&qkv, g_qkv);
    float* att; cudaGetSymbolAddress((void**)&att, g_att);

    static const size_t attn_smem = AT_SMEM_FLOATS * sizeof(float);  // ~152 KB
    cudaFuncSetAttribute(attn_tc_kernel,
                         cudaFuncAttributeMaxDynamicSharedMemorySize,
                         (int)attn_smem);

    init_tab_kernel<<<(S_ * 16 + 255) / 256, 256>>>();

    {   // QKV projection (bf16x3, fused RoPE on q/k tiles)
        dim3 grid(S_ / 128, O1_ / 64, B_);
        gemm_bf16_kernel<256, false, true><<<grid, 256>>>(w_qkv, x, nullptr, qkv, O1_);
    }

    l2norm_kernel<<<B_ * 2 * HID_, 256>>>(qkv);

    {   // Attention
        dim3 grid(S_ / 64, H_, B_);
        attn_tc_kernel<<<grid, 256, attn_smem>>>(qkv, att);
    }

    {   // Output projection (bf16x3 + bias)
        dim3 grid(S_ / 128, C_ / 64, B_);
        gemm_bf16_kernel<512, true, false><<<grid, 256>>>(w_out, att, b_out, out, C_);
    }
}

// round 11
// speedup vs baseline: 3.1906x; 1.0611x over previous
#include <cuda_runtime.h>
#include <cuda_bf16.h>
#include <math.h>
#include <stdint.h>

// ---------------------------------------------------------------------------
// Problem constants
//   x: (8, 256, 32, 32)  -> [b][c][s], s = 1024
//   w_qkv: (1536, 256), w_out: (256, 512), b_out: (256,)
//   HEADS=8, DIM_HEAD=64, SCALE=10, ROT_DIM=32 (16 freqs)
//   L2 norm over the SEQUENCE axis (per (b,h,d) row), per reference.
// ---------------------------------------------------------------------------
#define B_   8
#define C_   256
#define S_   1024
#define H_   8
#define D_   64
#define HID_ 512
#define O1_  1536

__device__ float g_qkv[B_ * O1_ * S_];     // [b][o][s]
__device__ float g_att[B_ * HID_ * S_];    // [b][h*64+d][s]
__device__ float g_sin[S_ * 16];
__device__ float g_cos[S_ * 16];

// ---------------------------------------------------------------------------
// MMA helpers
// ---------------------------------------------------------------------------
__device__ __forceinline__ void mma_tf32(float c[4],
    uint32_t a0, uint32_t a1, uint32_t a2, uint32_t a3,
    uint32_t b0, uint32_t b1)
{
    asm volatile(
        "mma.sync.aligned.m16n8k8.row.col.f32.tf32.tf32.f32 "
        "{%0,%1,%2,%3}, {%4,%5,%6,%7}, {%8,%9}, {%0,%1,%2,%3};"
        : "+f"(c[0]), "+f"(c[1]), "+f"(c[2]), "+f"(c[3])
        : "r"(a0), "r"(a1), "r"(a2), "r"(a3), "r"(b0), "r"(b1));
}

__device__ __forceinline__ void mma_bf16(float c[4],
    uint32_t a0, uint32_t a1, uint32_t a2, uint32_t a3,
    uint32_t b0, uint32_t b1)
{
    asm volatile(
        "mma.sync.aligned.m16n8k16.row.col.f32.bf16.bf16.f32 "
        "{%0,%1,%2,%3}, {%4,%5,%6,%7}, {%8,%9}, {%0,%1,%2,%3};"
        : "+f"(c[0]), "+f"(c[1]), "+f"(c[2]), "+f"(c[3])
        : "r"(a0), "r"(a1), "r"(a2), "r"(a3), "r"(b0), "r"(b1));
}

__device__ __forceinline__ void split_pack_bf16(float v0, float v1,
                                                uint32_t& hp, uint32_t& lp)
{
    __nv_bfloat16 h0 = __float2bfloat16_rn(v0);
    __nv_bfloat16 h1 = __float2bfloat16_rn(v1);
    __nv_bfloat16 l0 = __float2bfloat16_rn(v0 - __bfloat162float(h0));
    __nv_bfloat16 l1 = __float2bfloat16_rn(v1 - __bfloat162float(h1));
    __nv_bfloat162 hv = __halves2bfloat162(h0, h1);
    __nv_bfloat162 lv = __halves2bfloat162(l0, l1);
    hp = *(uint32_t*)&hv;
    lp = *(uint32_t*)&lv;
}

__device__ __forceinline__ void cp_async16(uint32_t s, const void* g) {
    asm volatile("cp.async.cg.shared.global [%0], [%1], 16;" :: "r"(s), "l"(g));
}
#define CP_COMMIT() asm volatile("cp.async.commit_group;")
#define CP_WAIT0()  asm volatile("cp.async.wait_group 0;")

// ---------------------------------------------------------------------------
// 0) sin/cos table
// ---------------------------------------------------------------------------
__global__ void init_tab_kernel() {
    int id = blockIdx.x * blockDim.x + threadIdx.x;
    if (id >= S_ * 16) return;
    int s = id >> 4;
    int j = id & 15;
    float invf = (float)pow(10000.0, -(double)j / 16.0);
    double ang = (double)s * (double)invf;
    g_sin[id] = (float)sin(ang);
    g_cos[id] = (float)cos(ang);
}

// ---------------------------------------------------------------------------
// 1+4) bf16 3-term split GEMM (m16n8k16), fp32-accurate to ~1.5e-5.
// ---------------------------------------------------------------------------
template<int KDIM, bool BIAS, bool ROPE>
__global__ __launch_bounds__(256) void gemm_bf16_kernel(
    const float* __restrict__ W, const float* __restrict__ X,
    const float* __restrict__ bias, float* __restrict__ C, int Mtot)
{
    __shared__ uint32_t Ah[8 * 72], Al[8 * 72];
    __shared__ uint32_t Bh[8 * 136], Bl[8 * 136];

    const int tid  = threadIdx.x;
    const int lane = tid & 31, warp = tid >> 5;
    const int g = lane >> 2, tg = lane & 3;
    const int wm = warp & 1, wn = warp >> 1;
    const int mbase = wm * 32, nbase = wn * 32;

    const int s0 = blockIdx.x * 128;
    const int o0 = blockIdx.y * 64;
    const int b  = blockIdx.z;

    const float* Wp = W + (size_t)o0 * KDIM;
    const float* Xp = X + (size_t)b * KDIM * S_ + s0;

    const int am = tid >> 2, akq = tid & 3;
    const int bp = tid >> 5, bnq = tid & 31;

    float4 w4  = *(const float4*)(Wp + (size_t)am * KDIM + akq * 4);
    float4 x4a = *(const float4*)(Xp + (size_t)(2 * bp) * S_ + bnq * 4);
    float4 x4b = *(const float4*)(Xp + (size_t)(2 * bp + 1) * S_ + bnq * 4);

    float acc[2][4][4] = {};

    for (int k0 = 0; k0 < KDIM; k0 += 16) {
        __syncthreads();
        {
            uint32_t hp, lp;
            split_pack_bf16(w4.x, w4.y, hp, lp);
            Ah[(2 * akq + 0) * 72 + am] = hp; Al[(2 * akq + 0) * 72 + am] = lp;
            split_pack_bf16(w4.z, w4.w, hp, lp);
            Ah[(2 * akq + 1) * 72 + am] = hp; Al[(2 * akq + 1) * 72 + am] = lp;
            uint32_t h0, l0, h1, l1, h2, l2, h3, l3;
            split_pack_bf16(x4a.x, x4b.x, h0, l0);
            split_pack_bf16(x4a.y, x4b.y, h1, l1);
            split_pack_bf16(x4a.z, x4b.z, h2, l2);
            split_pack_bf16(x4a.w, x4b.w, h3, l3);
            *(uint4*)&Bh[bp * 136 + bnq * 4] = make_uint4(h0, h1, h2, h3);
            *(uint4*)&Bl[bp * 136 + bnq * 4] = make_uint4(l0, l1, l2, l3);
        }
        __syncthreads();

        if (k0 + 16 < KDIM) {
            w4  = *(const float4*)(Wp + (size_t)am * KDIM + k0 + 16 + akq * 4);
            x4a = *(const float4*)(Xp + (size_t)(k0 + 16 + 2 * bp) * S_ + bnq * 4);
            x4b = *(const float4*)(Xp + (size_t)(k0 + 16 + 2 * bp + 1) * S_ + bnq * 4);
        }

        uint32_t ah[2][4], al[2][4];
#pragma unroll
        for (int mt = 0; mt < 2; mt++) {
            int r = mbase + mt * 16 + g;
            ah[mt][0] = Ah[tg * 72 + r];
            ah[mt][1] = Ah[tg * 72 + r + 8];
            ah[mt][2] = Ah[(tg + 4) * 72 + r];
            ah[mt][3] = Ah[(tg + 4) * 72 + r + 8];
            al[mt][0] = Al[tg * 72 + r];
            al[mt][1] = Al[tg * 72 + r + 8];
            al[mt][2] = Al[(tg + 4) * 72 + r];
            al[mt][3] = Al[(tg + 4) * 72 + r + 8];
        }
        uint32_t bh[4][2], bl[4][2];
#pragma unroll
        for (int nt = 0; nt < 4; nt++) {
            int n = nbase + nt * 8 + g;
            bh[nt][0] = Bh[tg * 136 + n];
            bh[nt][1] = Bh[(tg + 4) * 136 + n];
            bl[nt][0] = Bl[tg * 136 + n];
            bl[nt][1] = Bl[(tg + 4) * 136 + n];
        }
#pragma unroll
        for (int mt = 0; mt < 2; mt++)
#pragma unroll
            for (int nt = 0; nt < 4; nt++) {
                mma_bf16(acc[mt][nt], ah[mt][0], ah[mt][1], ah[mt][2], ah[mt][3], bh[nt][0], bh[nt][1]);
                mma_bf16(acc[mt][nt], ah[mt][0], ah[mt][1], ah[mt][2], ah[mt][3], bl[nt][0], bl[nt][1]);
                mma_bf16(acc[mt][nt], al[mt][0], al[mt][1], al[mt][2], al[mt][3], bh[nt][0], bh[nt][1]);
            }
    }

    if (ROPE && o0 < 2 * HID_ && wm == 0) {
#pragma unroll
        for (int rh = 0; rh < 2; rh++) {
            int d = rh * 8 + g;
#pragma unroll
            for (int nt = 0; nt < 4; nt++)
#pragma unroll
                for (int cl = 0; cl < 2; cl++) {
                    int col = s0 + nbase + nt * 8 + tg * 2 + cl;
                    float cs = g_cos[col * 16 + d];
                    float sn = g_sin[col * 16 + d];
                    float x = acc[0][nt][rh * 2 + cl];
                    float y = acc[1][nt][rh * 2 + cl];
                    acc[0][nt][rh * 2 + cl] = x * cs - y * sn;
                    acc[1][nt][rh * 2 + cl] = y * cs + x * sn;
                }
        }
    }

    float* Cp = C + ((size_t)b * Mtot + o0) * S_ + s0;
#pragma unroll
    for (int mt = 0; mt < 2; mt++)
#pragma unroll
        for (int rh = 0; rh < 2; rh++) {
            int row = mbase + mt * 16 + rh * 8 + g;
            float bv = BIAS ? bias[o0 + row] : 0.f;
#pragma unroll
            for (int nt = 0; nt < 4; nt++) {
                int col = nbase + nt * 8 + tg * 2;
                float2 v2 = make_float2(acc[mt][nt][rh * 2 + 0] + bv,
                                        acc[mt][nt][rh * 2 + 1] + bv);
                *(float2*)(Cp + (size_t)row * S_ + col) = v2;
            }
        }
}

// ---------------------------------------------------------------------------
// 2b) L2 norm over the sequence axis
// ---------------------------------------------------------------------------
__global__ __launch_bounds__(256) void l2norm_kernel(float* __restrict__ qkv)
{
    int row = blockIdx.x;
    int b = row >> 10;
    int o = row & 1023;
    float* p = qkv + ((size_t)b * O1_ + o) * S_;

    int tid = threadIdx.x;
    float4 v = *(float4*)(p + tid * 4);
    float ss = v.x * v.x + v.y * v.y + v.z * v.z + v.w * v.w;
#pragma unroll
    for (int off = 16; off; off >>= 1)
        ss += __shfl_xor_sync(0xffffffffu, ss, off);

    __shared__ float wss[8];
    if ((tid & 31) == 0) wss[tid >> 5] = ss;
    __syncthreads();
    if (tid < 32) {
        float t = (tid < 8) ? wss[tid] : 0.f;
#pragma unroll
        for (int off = 4; off; off >>= 1)
            t += __shfl_xor_sync(0xffffffffu, t, off);
        if (tid == 0) wss[0] = t;
    }
    __syncthreads();

    float inv = 1.0f / fmaxf(sqrtf(wss[0]), 1e-12f);
    v.x *= inv; v.y *= inv; v.z *= inv; v.w *= inv;
    *(float4*)(p + tid * 4) = v;
}

// ---------------------------------------------------------------------------
// 3) Attention, 2 blocks/SM version:
//    - single K/V buffer (87 KB smem), cross-block overlap hides load latency
//    - __launch_bounds__(256, 2): regs capped at 128
//    - each 128-j iteration processed in two 16-j halves per warp to shrink
//      the live register set (sacc 16 instead of 32)
//    Strides: Qs 72, Ks 136, Vs 132, Ot 68 — all conflict-free (unchanged).
// ---------------------------------------------------------------------------
#define AT_QS 0            // 64*72  = 4608   (reused as Ot[d][i] stride 68)
#define AT_KS 4608         // 64*136 = 8704
#define AT_VS 13312        // 64*132 = 8448
#define AT_L  21760        // 64
#define AT_SMEM_FLOATS 21824

__global__ __launch_bounds__(256, 2) void attn_tc_kernel(
    const float* __restrict__ qkv, float* __restrict__ att)
{
    extern __shared__ float sm[];
    float* Qs  = sm + AT_QS;
    float* Ks  = sm + AT_KS;
    float* Vs  = sm + AT_VS;
    float* Lsm = sm + AT_L;

    const int tid  = threadIdx.x;
    const int lane = tid & 31;
    const int warp = tid >> 5;
    const int g  = lane >> 2;
    const int tg = lane & 3;
    const int wi = warp & 1;
    const int wq = warp >> 1;
    const int ib = wi * 32;
    const int jb = wq * 32;
    const int fg = (g >> 1) | ((g & 1) << 2);   // K column permutation

    const int i0 = blockIdx.x * 64;
    const int h  = blockIdx.y;
    const int b  = blockIdx.z;

    const float* Qg = qkv + ((size_t)b * O1_ + h * D_) * S_;
    const float* Kg = Qg + (size_t)HID_ * S_;
    const float* Vg = Qg + (size_t)(2 * HID_) * S_;

    uint32_t smbase = (uint32_t)__cvta_generic_to_shared(sm);

    // Q tile [d][i], stride 72
    for (int v = tid; v < 1024; v += 256) {
        int d = v >> 4, iq = v & 15;
        *(float4*)&Qs[d * 72 + iq * 4] =
            *(const float4*)(Qg + (size_t)d * S_ + i0 + iq * 4);
    }
    if (tid < 64) Lsm[tid] = 0.f;

    const int ld = tid >> 5, ljq = tid & 31;

    float oacc[2][8][4] = {};
    float l_acc[2][2]   = {};

    for (int it = 0; it < 8; it++) {
        const int j0 = it * 128;
        __syncthreads();   // all warps done with previous K/V (and Q ready)
        // load K,V tile (single buffer; 2 blocks/SM overlap this wait)
#pragma unroll
        for (int r = 0; r < 8; r++) {
            int d = ld + r * 8;
            cp_async16(smbase + (AT_KS + d * 136 + ljq * 4) * 4,
                       Kg + (size_t)d * S_ + j0 + ljq * 4);
            cp_async16(smbase + (AT_VS + d * 132 + ljq * 4) * 4,
                       Vg + (size_t)d * S_ + j0 + ljq * 4);
        }
        CP_COMMIT();
        CP_WAIT0();
        __syncthreads();

        // two 16-j halves per warp: S(16j) -> exp -> O(16j)
#pragma unroll
        for (int hf = 0; hf < 2; hf++) {
            const int jh = jb + hf * 16;

            float sacc[2][2][4] = {};
#pragma unroll
            for (int kk = 0; kk < 8; kk++) {
                const int k0 = kk * 8;
                uint32_t a[2][4];
#pragma unroll
                for (int mt = 0; mt < 2; mt++) {
                    int r = ib + mt * 16 + g;
                    a[mt][0] = __float_as_uint(Qs[(k0 + tg) * 72 + r]);
                    a[mt][1] = __float_as_uint(Qs[(k0 + tg) * 72 + r + 8]);
                    a[mt][2] = __float_as_uint(Qs[(k0 + tg + 4) * 72 + r]);
                    a[mt][3] = __float_as_uint(Qs[(k0 + tg + 4) * 72 + r + 8]);
                }
                uint32_t bb[2][2];
#pragma unroll
                for (int nt = 0; nt < 2; nt++) {
                    int jc = jh + nt * 8 + fg;
                    bb[nt][0] = __float_as_uint(Ks[(k0 + tg) * 136 + jc]);
                    bb[nt][1] = __float_as_uint(Ks[(k0 + tg + 4) * 136 + jc]);
                }
#pragma unroll
                for (int mt = 0; mt < 2; mt++)
#pragma unroll
                    for (int nt = 0; nt < 2; nt++)
                        mma_tf32(sacc[mt][nt], a[mt][0], a[mt][1], a[mt][2], a[mt][3],
                                 bb[nt][0], bb[nt][1]);
            }

            // exp in place + row sums
#pragma unroll
            for (int mt = 0; mt < 2; mt++)
#pragma unroll
                for (int nt = 0; nt < 2; nt++) {
                    float p0 = __expf(10.f * sacc[mt][nt][0]);
                    float p1 = __expf(10.f * sacc[mt][nt][1]);
                    float p2 = __expf(10.f * sacc[mt][nt][2]);
                    float p3 = __expf(10.f * sacc[mt][nt][3]);
                    sacc[mt][nt][0] = p0; sacc[mt][nt][1] = p1;
                    sacc[mt][nt][2] = p2; sacc[mt][nt][3] = p3;
                    l_acc[mt][0] += p0 + p1;
                    l_acc[mt][1] += p2 + p3;
                }

            // O phase for this half: k = 16 j's (2 ks steps), n = all 64 d
#pragma unroll
            for (int ks = 0; ks < 2; ks++) {
                const int jk = jh + ks * 8;
                uint32_t bb[8][2];
#pragma unroll
                for (int nt = 0; nt < 8; nt++) {
                    int dc = nt * 8 + g;
                    bb[nt][0] = __float_as_uint(Vs[dc * 132 + jk + tg]);
                    bb[nt][1] = __float_as_uint(Vs[dc * 132 + jk + tg + 4]);
                }
#pragma unroll
                for (int mt = 0; mt < 2; mt++) {
                    uint32_t a0 = __float_as_uint(sacc[mt][ks][0]);
                    uint32_t a1 = __float_as_uint(sacc[mt][ks][2]);
                    uint32_t a2 = __float_as_uint(sacc[mt][ks][1]);
                    uint32_t a3 = __float_as_uint(sacc[mt][ks][3]);
#pragma unroll
                    for (int nt = 0; nt < 8; nt++)
                        mma_tf32(oacc[mt][nt], a0, a1, a2, a3, bb[nt][0], bb[nt][1]);
                }
            }
        }
    }

    // row sums: reduce over tg lanes, merge 4 j-warps via atomicAdd
#pragma unroll
    for (int mt = 0; mt < 2; mt++)
#pragma unroll
        for (int rh = 0; rh < 2; rh++) {
            float l = l_acc[mt][rh];
            l += __shfl_xor_sync(0xffffffffu, l, 1);
            l += __shfl_xor_sync(0xffffffffu, l, 2);
            if (tg == 0)
                atomicAdd(&Lsm[ib + mt * 16 + rh * 8 + g], l);
        }
    __syncthreads();

    // staged reduction of partial O across 4 j-warps into Ot=Qs[d][i] (str 68)
#pragma unroll
    for (int r = 0; r < 4; r++) {
        if (wq == r) {
#pragma unroll
            for (int mt = 0; mt < 2; mt++)
#pragma unroll
                for (int nt = 0; nt < 8; nt++)
#pragma unroll
                    for (int c = 0; c < 4; c++) {
                        int row = ib + mt * 16 + g + ((c >> 1) << 3);
                        int col = nt * 8 + tg * 2 + (c & 1);
                        if (r == 0) Qs[col * 68 + row] = oacc[mt][nt][c];
                        else        Qs[col * 68 + row] += oacc[mt][nt][c];
                    }
        }
        __syncthreads();
    }

    if (tid < 64) Lsm[tid] = 1.0f / Lsm[tid];
    __syncthreads();

    // normalized, coalesced store [d][s]
    float* Ap = att + ((size_t)b * HID_ + h * D_) * S_ + i0;
    for (int v = tid; v < 1024; v += 256) {
        int d = v >> 4, iq = v & 15;
        float4 o = *(float4*)&Qs[d * 68 + iq * 4];
        o.x *= Lsm[iq * 4 + 0];
        o.y *= Lsm[iq * 4 + 1];
        o.z *= Lsm[iq * 4 + 2];
        o.w *= Lsm[iq * 4 + 3];
        *(float4*)(Ap + (size_t)d * S_ + iq * 4) = o;
    }
}

// ---------------------------------------------------------------------------
// Launch
// ---------------------------------------------------------------------------
extern "C" void kernel_launch(void* const* d_in, const int* in_sizes, int n_in,
                              void* d_out, int out_size)
{
    const float* x     = (const float*)d_in[0];
    const float* w_qkv = (const float*)d_in[1];
    const float* w_out = (const float*)d_in[2];
    const float* b_out = (const float*)d_in[3];
    float* out = (float*)d_out;

    float* qkv; cudaGetSymbolAddress((void**)&qkv, g_qkv);
    float* att; cudaGetSymbolAddress((void**)&att, g_att);

    static const size_t attn_smem = AT_SMEM_FLOATS * sizeof(float);  // ~87 KB
    cudaFuncSetAttribute(attn_tc_kernel,
                         cudaFuncAttributeMaxDynamicSharedMemorySize,
                         (int)attn_smem);

    init_tab_kernel<<<(S_ * 16 + 255) / 256, 256>>>();

    {   // QKV projection (bf16x3, fused RoPE on q/k tiles)
        dim3 grid(S_ / 128, O1_ / 64, B_);
        gemm_bf16_kernel<256, false, true><<<grid, 256>>>(w_qkv, x, nullptr, qkv, O1_);
    }

    l2norm_kernel<<<B_ * 2 * HID_, 256>>>(qkv);

    {   // Attention (2 blocks/SM)
        dim3 grid(S_ / 64, H_, B_);
        attn_tc_kernel<<<grid, 256, attn_smem>>>(qkv, att);
    }

    {   // Output projection (bf16x3 + bias)
        dim3 grid(S_ / 128, C_ / 64, B_);
        gemm_bf16_kernel<512, true, false><<<grid, 256>>>(w_out, att, b_out, out, C_);
    }
}

// round 12
// speedup vs baseline: 3.2078x; 1.0054x over previous
#include <cuda_runtime.h>
#include <cuda_bf16.h>
#include <math.h>
#include <stdint.h>

// ---------------------------------------------------------------------------
// Problem constants
//   x: (8, 256, 32, 32)  -> [b][c][s], s = 1024
//   w_qkv: (1536, 256), w_out: (256, 512), b_out: (256,)
//   HEADS=8, DIM_HEAD=64, SCALE=10, ROT_DIM=32 (16 freqs)
//   L2 norm over the SEQUENCE axis (per (b,h,d) row), per reference.
// ---------------------------------------------------------------------------
#define B_   8
#define C_   256
#define S_   1024
#define H_   8
#define D_   64
#define HID_ 512
#define O1_  1536

__device__ float g_qkv[B_ * O1_ * S_];     // [b][o][s]
__device__ float g_att[B_ * HID_ * S_];    // [b][h*64+d][s]
__device__ float g_sin[S_ * 16];
__device__ float g_cos[S_ * 16];

// ---------------------------------------------------------------------------
// MMA helpers
// ---------------------------------------------------------------------------
__device__ __forceinline__ void mma_tf32(float c[4],
    uint32_t a0, uint32_t a1, uint32_t a2, uint32_t a3,
    uint32_t b0, uint32_t b1)
{
    asm volatile(
        "mma.sync.aligned.m16n8k8.row.col.f32.tf32.tf32.f32 "
        "{%0,%1,%2,%3}, {%4,%5,%6,%7}, {%8,%9}, {%0,%1,%2,%3};"
        : "+f"(c[0]), "+f"(c[1]), "+f"(c[2]), "+f"(c[3])
        : "r"(a0), "r"(a1), "r"(a2), "r"(a3), "r"(b0), "r"(b1));
}

__device__ __forceinline__ void mma_bf16(float c[4],
    uint32_t a0, uint32_t a1, uint32_t a2, uint32_t a3,
    uint32_t b0, uint32_t b1)
{
    asm volatile(
        "mma.sync.aligned.m16n8k16.row.col.f32.bf16.bf16.f32 "
        "{%0,%1,%2,%3}, {%4,%5,%6,%7}, {%8,%9}, {%0,%1,%2,%3};"
        : "+f"(c[0]), "+f"(c[1]), "+f"(c[2]), "+f"(c[3])
        : "r"(a0), "r"(a1), "r"(a2), "r"(a3), "r"(b0), "r"(b1));
}

__device__ __forceinline__ void split_pack_bf16(float v0, float v1,
                                                uint32_t& hp, uint32_t& lp)
{
    __nv_bfloat16 h0 = __float2bfloat16_rn(v0);
    __nv_bfloat16 h1 = __float2bfloat16_rn(v1);
    __nv_bfloat16 l0 = __float2bfloat16_rn(v0 - __bfloat162float(h0));
    __nv_bfloat16 l1 = __float2bfloat16_rn(v1 - __bfloat162float(h1));
    __nv_bfloat162 hv = __halves2bfloat162(h0, h1);
    __nv_bfloat162 lv = __halves2bfloat162(l0, l1);
    hp = *(uint32_t*)&hv;
    lp = *(uint32_t*)&lv;
}

__device__ __forceinline__ void cp_async16(uint32_t s, const void* g) {
    asm volatile("cp.async.cg.shared.global [%0], [%1], 16;" :: "r"(s), "l"(g));
}
#define CP_COMMIT() asm volatile("cp.async.commit_group;")
#define CP_WAIT1()  asm volatile("cp.async.wait_group 1;")
#define CP_WAIT0()  asm volatile("cp.async.wait_group 0;")

// ---------------------------------------------------------------------------
// 0) sin/cos table
// ---------------------------------------------------------------------------
__global__ void init_tab_kernel() {
    int id = blockIdx.x * blockDim.x + threadIdx.x;
    if (id >= S_ * 16) return;
    int s = id >> 4;
    int j = id & 15;
    float invf = (float)pow(10000.0, -(double)j / 16.0);
    double ang = (double)s * (double)invf;
    g_sin[id] = (float)sin(ang);
    g_cos[id] = (float)cos(ang);
}

// ---------------------------------------------------------------------------
// 1+4) bf16 3-term split GEMM (m16n8k16), fp32-accurate to ~1.5e-5.
// ---------------------------------------------------------------------------
template<int KDIM, bool BIAS, bool ROPE>
__global__ __launch_bounds__(256) void gemm_bf16_kernel(
    const float* __restrict__ W, const float* __restrict__ X,
    const float* __restrict__ bias, float* __restrict__ C, int Mtot)
{
    __shared__ uint32_t Ah[8 * 72], Al[8 * 72];
    __shared__ uint32_t Bh[8 * 136], Bl[8 * 136];

    const int tid  = threadIdx.x;
    const int lane = tid & 31, warp = tid >> 5;
    const int g = lane >> 2, tg = lane & 3;
    const int wm = warp & 1, wn = warp >> 1;
    const int mbase = wm * 32, nbase = wn * 32;

    const int s0 = blockIdx.x * 128;
    const int o0 = blockIdx.y * 64;
    const int b  = blockIdx.z;

    const float* Wp = W + (size_t)o0 * KDIM;
    const float* Xp = X + (size_t)b * KDIM * S_ + s0;

    const int am = tid >> 2, akq = tid & 3;
    const int bp = tid >> 5, bnq = tid & 31;

    float4 w4  = *(const float4*)(Wp + (size_t)am * KDIM + akq * 4);
    float4 x4a = *(const float4*)(Xp + (size_t)(2 * bp) * S_ + bnq * 4);
    float4 x4b = *(const float4*)(Xp + (size_t)(2 * bp + 1) * S_ + bnq * 4);

    float acc[2][4][4] = {};

    for (int k0 = 0; k0 < KDIM; k0 += 16) {
        __syncthreads();
        {
            uint32_t hp, lp;
            split_pack_bf16(w4.x, w4.y, hp, lp);
            Ah[(2 * akq + 0) * 72 + am] = hp; Al[(2 * akq + 0) * 72 + am] = lp;
            split_pack_bf16(w4.z, w4.w, hp, lp);
            Ah[(2 * akq + 1) * 72 + am] = hp; Al[(2 * akq + 1) * 72 + am] = lp;
            uint32_t h0, l0, h1, l1, h2, l2, h3, l3;
            split_pack_bf16(x4a.x, x4b.x, h0, l0);
            split_pack_bf16(x4a.y, x4b.y, h1, l1);
            split_pack_bf16(x4a.z, x4b.z, h2, l2);
            split_pack_bf16(x4a.w, x4b.w, h3, l3);
            *(uint4*)&Bh[bp * 136 + bnq * 4] = make_uint4(h0, h1, h2, h3);
            *(uint4*)&Bl[bp * 136 + bnq * 4] = make_uint4(l0, l1, l2, l3);
        }
        __syncthreads();

        if (k0 + 16 < KDIM) {
            w4  = *(const float4*)(Wp + (size_t)am * KDIM + k0 + 16 + akq * 4);
            x4a = *(const float4*)(Xp + (size_t)(k0 + 16 + 2 * bp) * S_ + bnq * 4);
            x4b = *(const float4*)(Xp + (size_t)(k0 + 16 + 2 * bp + 1) * S_ + bnq * 4);
        }

        uint32_t ah[2][4], al[2][4];
#pragma unroll
        for (int mt = 0; mt < 2; mt++) {
            int r = mbase + mt * 16 + g;
            ah[mt][0] = Ah[tg * 72 + r];
            ah[mt][1] = Ah[tg * 72 + r + 8];
            ah[mt][2] = Ah[(tg + 4) * 72 + r];
            ah[mt][3] = Ah[(tg + 4) * 72 + r + 8];
            al[mt][0] = Al[tg * 72 + r];
            al[mt][1] = Al[tg * 72 + r + 8];
            al[mt][2] = Al[(tg + 4) * 72 + r];
            al[mt][3] = Al[(tg + 4) * 72 + r + 8];
        }
        uint32_t bh[4][2], bl[4][2];
#pragma unroll
        for (int nt = 0; nt < 4; nt++) {
            int n = nbase + nt * 8 + g;
            bh[nt][0] = Bh[tg * 136 + n];
            bh[nt][1] = Bh[(tg + 4) * 136 + n];
            bl[nt][0] = Bl[tg * 136 + n];
            bl[nt][1] = Bl[(tg + 4) * 136 + n];
        }
#pragma unroll
        for (int mt = 0; mt < 2; mt++)
#pragma unroll
            for (int nt = 0; nt < 4; nt++) {
                mma_bf16(acc[mt][nt], ah[mt][0], ah[mt][1], ah[mt][2], ah[mt][3], bh[nt][0], bh[nt][1]);
                mma_bf16(acc[mt][nt], ah[mt][0], ah[mt][1], ah[mt][2], ah[mt][3], bl[nt][0], bl[nt][1]);
                mma_bf16(acc[mt][nt], al[mt][0], al[mt][1], al[mt][2], al[mt][3], bh[nt][0], bh[nt][1]);
            }
    }

    if (ROPE && o0 < 2 * HID_ && wm == 0) {
#pragma unroll
        for (int rh = 0; rh < 2; rh++) {
            int d = rh * 8 + g;
#pragma unroll
            for (int nt = 0; nt < 4; nt++)
#pragma unroll
                for (int cl = 0; cl < 2; cl++) {
                    int col = s0 + nbase + nt * 8 + tg * 2 + cl;
                    float cs = g_cos[col * 16 + d];
                    float sn = g_sin[col * 16 + d];
                    float x = acc[0][nt][rh * 2 + cl];
                    float y = acc[1][nt][rh * 2 + cl];
                    acc[0][nt][rh * 2 + cl] = x * cs - y * sn;
                    acc[1][nt][rh * 2 + cl] = y * cs + x * sn;
                }
        }
    }

    float* Cp = C + ((size_t)b * Mtot + o0) * S_ + s0;
#pragma unroll
    for (int mt = 0; mt < 2; mt++)
#pragma unroll
        for (int rh = 0; rh < 2; rh++) {
            int row = mbase + mt * 16 + rh * 8 + g;
            float bv = BIAS ? bias[o0 + row] : 0.f;
#pragma unroll
            for (int nt = 0; nt < 4; nt++) {
                int col = nbase + nt * 8 + tg * 2;
                float2 v2 = make_float2(acc[mt][nt][rh * 2 + 0] + bv,
                                        acc[mt][nt][rh * 2 + 1] + bv);
                *(float2*)(Cp + (size_t)row * S_ + col) = v2;
            }
        }
}

// ---------------------------------------------------------------------------
// 2b) L2 norm over the sequence axis
// ---------------------------------------------------------------------------
__global__ __launch_bounds__(256) void l2norm_kernel(float* __restrict__ qkv)
{
    int row = blockIdx.x;
    int b = row >> 10;
    int o = row & 1023;
    float* p = qkv + ((size_t)b * O1_ + o) * S_;

    int tid = threadIdx.x;
    float4 v = *(float4*)(p + tid * 4);
    float ss = v.x * v.x + v.y * v.y + v.z * v.z + v.w * v.w;
#pragma unroll
    for (int off = 16; off; off >>= 1)
        ss += __shfl_xor_sync(0xffffffffu, ss, off);

    __shared__ float wss[8];
    if ((tid & 31) == 0) wss[tid >> 5] = ss;
    __syncthreads();
    if (tid < 32) {
        float t = (tid < 8) ? wss[tid] : 0.f;
#pragma unroll
        for (int off = 4; off; off >>= 1)
            t += __shfl_xor_sync(0xffffffffu, t, off);
        if (tid == 0) wss[0] = t;
    }
    __syncthreads();

    float inv = 1.0f / fmaxf(sqrtf(wss[0]), 1e-12f);
    v.x *= inv; v.y *= inv; v.z *= inv; v.w *= inv;
    *(float4*)(p + tid * 4) = v;
}

// ---------------------------------------------------------------------------
// 3) Attention: 2 blocks/SM AND double-buffered cp.async (j-tile 64).
//    16 iterations of 64 j; each warp owns a 16-j slice (wq*16).
//    smem (floats): Qs 64x72 @0 (reused as Ot stride 68), K0/K1 64x72,
//    V0/V1 64x68, L 64  -> 22592 floats = 88.3 KB -> 2 blocks/SM.
//    Strides: Qs/Ks 72 (≡8 mod 32, conflict-free for tg-indexed rows),
//    Vs 68 (≡4 mod 32, conflict-free for g-indexed rows), Ot 68.
// ---------------------------------------------------------------------------
#define AT_QS 0            // 64*72 = 4608
#define AT_K0 4608         // 64*72 = 4608
#define AT_K1 9216
#define AT_V0 13824        // 64*68 = 4352
#define AT_V1 18176
#define AT_L  22528        // 64
#define AT_SMEM_FLOATS 22592

__global__ __launch_bounds__(256, 2) void attn_tc_kernel(
    const float* __restrict__ qkv, float* __restrict__ att)
{
    extern __shared__ float sm[];
    float* Qs  = sm + AT_QS;
    float* Lsm = sm + AT_L;

    const int tid  = threadIdx.x;
    const int lane = tid & 31;
    const int warp = tid >> 5;
    const int g  = lane >> 2;
    const int tg = lane & 3;
    const int wi = warp & 1;
    const int wq = warp >> 1;          // 0..3: 16-j slice
    const int ib = wi * 32;
    const int jh = wq * 16;            // this warp's j offset within the tile
    const int fg = (g >> 1) | ((g & 1) << 2);   // K column permutation

    const int i0 = blockIdx.x * 64;
    const int h  = blockIdx.y;
    const int b  = blockIdx.z;

    const float* Qg = qkv + ((size_t)b * O1_ + h * D_) * S_;
    const float* Kg = Qg + (size_t)HID_ * S_;
    const float* Vg = Qg + (size_t)(2 * HID_) * S_;

    uint32_t smbase = (uint32_t)__cvta_generic_to_shared(sm);

    // Q tile [d][i], stride 72
    for (int v = tid; v < 1024; v += 256) {
        int d = v >> 4, iq = v & 15;
        *(float4*)&Qs[d * 72 + iq * 4] =
            *(const float4*)(Qg + (size_t)d * S_ + i0 + iq * 4);
    }
    if (tid < 64) Lsm[tid] = 0.f;

    // K/V tile loader: 64 d-rows x 64 j floats; thread t covers
    // d = (t>>4) + 16r (r<4), j-quad = t&15  -> 4+4 cp.async per thread.
    const int ldd = tid >> 4, ljq = tid & 15;
    auto issue_kv = [&](int buf, int j0) {
        uint32_t koff = (buf ? AT_K1 : AT_K0);
        uint32_t voff = (buf ? AT_V1 : AT_V0);
#pragma unroll
        for (int r = 0; r < 4; r++) {
            int d = ldd + r * 16;
            cp_async16(smbase + (koff + d * 72 + ljq * 4) * 4,
                       Kg + (size_t)d * S_ + j0 + ljq * 4);
            cp_async16(smbase + (voff + d * 68 + ljq * 4) * 4,
                       Vg + (size_t)d * S_ + j0 + ljq * 4);
        }
    };

    issue_kv(0, 0);
    CP_COMMIT();

    float oacc[2][8][4] = {};
    float l_acc[2][2]   = {};

    for (int it = 0; it < 16; it++) {
        const int cur = it & 1;
        __syncthreads();   // prev compute done with buf cur^1 (about to refill)
        if (it + 1 < 16) {
            issue_kv(cur ^ 1, (it + 1) * 64);
            CP_COMMIT();
            CP_WAIT1();    // wait for buf cur; next's group stays in flight
        } else {
            CP_WAIT0();
        }
        __syncthreads();   // buf cur visible to all warps

        const float* Ks = sm + (cur ? AT_K1 : AT_K0);
        const float* Vs = sm + (cur ? AT_V1 : AT_V0);

        // ---- S phase: S[32 i][16 j] per warp (K columns permuted by fg)
        float sacc[2][2][4] = {};
#pragma unroll
        for (int kk = 0; kk < 8; kk++) {
            const int k0 = kk * 8;
            uint32_t a[2][4];
#pragma unroll
            for (int mt = 0; mt < 2; mt++) {
                int r = ib + mt * 16 + g;
                a[mt][0] = __float_as_uint(Qs[(k0 + tg) * 72 + r]);
                a[mt][1] = __float_as_uint(Qs[(k0 + tg) * 72 + r + 8]);
                a[mt][2] = __float_as_uint(Qs[(k0 + tg + 4) * 72 + r]);
                a[mt][3] = __float_as_uint(Qs[(k0 + tg + 4) * 72 + r + 8]);
            }
            uint32_t bb[2][2];
#pragma unroll
            for (int nt = 0; nt < 2; nt++) {
                int jc = jh + nt * 8 + fg;
                bb[nt][0] = __float_as_uint(Ks[(k0 + tg) * 72 + jc]);
                bb[nt][1] = __float_as_uint(Ks[(k0 + tg + 4) * 72 + jc]);
            }
#pragma unroll
            for (int mt = 0; mt < 2; mt++)
#pragma unroll
                for (int nt = 0; nt < 2; nt++)
                    mma_tf32(sacc[mt][nt], a[mt][0], a[mt][1], a[mt][2], a[mt][3],
                             bb[nt][0], bb[nt][1]);
        }

        // ---- exp in place + row sums
#pragma unroll
        for (int mt = 0; mt < 2; mt++)
#pragma unroll
            for (int nt = 0; nt < 2; nt++) {
                float p0 = __expf(10.f * sacc[mt][nt][0]);
                float p1 = __expf(10.f * sacc[mt][nt][1]);
                float p2 = __expf(10.f * sacc[mt][nt][2]);
                float p3 = __expf(10.f * sacc[mt][nt][3]);
                sacc[mt][nt][0] = p0; sacc[mt][nt][1] = p1;
                sacc[mt][nt][2] = p2; sacc[mt][nt][3] = p3;
                l_acc[mt][0] += p0 + p1;
                l_acc[mt][1] += p2 + p3;
            }

        // ---- O phase: P (registers) x V^T, n = all 64 d, k = 16 j
#pragma unroll
        for (int ks = 0; ks < 2; ks++) {
            const int jk = jh + ks * 8;
            uint32_t bb[8][2];
#pragma unroll
            for (int nt = 0; nt < 8; nt++) {
                int dc = nt * 8 + g;
                bb[nt][0] = __float_as_uint(Vs[dc * 68 + jk + tg]);
                bb[nt][1] = __float_as_uint(Vs[dc * 68 + jk + tg + 4]);
            }
#pragma unroll
            for (int mt = 0; mt < 2; mt++) {
                uint32_t a0 = __float_as_uint(sacc[mt][ks][0]);
                uint32_t a1 = __float_as_uint(sacc[mt][ks][2]);
                uint32_t a2 = __float_as_uint(sacc[mt][ks][1]);
                uint32_t a3 = __float_as_uint(sacc[mt][ks][3]);
#pragma unroll
                for (int nt = 0; nt < 8; nt++)
                    mma_tf32(oacc[mt][nt], a0, a1, a2, a3, bb[nt][0], bb[nt][1]);
            }
        }
    }

    // ---- row sums: reduce over tg lanes, merge 4 j-warps via atomicAdd
#pragma unroll
    for (int mt = 0; mt < 2; mt++)
#pragma unroll
        for (int rh = 0; rh < 2; rh++) {
            float l = l_acc[mt][rh];
            l += __shfl_xor_sync(0xffffffffu, l, 1);
            l += __shfl_xor_sync(0xffffffffu, l, 2);
            if (tg == 0)
                atomicAdd(&Lsm[ib + mt * 16 + rh * 8 + g], l);
        }
    __syncthreads();

    // ---- staged reduction of partial O across 4 j-warps into Ot=Qs (str 68)
#pragma unroll
    for (int r = 0; r < 4; r++) {
        if (wq == r) {
#pragma unroll
            for (int mt = 0; mt < 2; mt++)
#pragma unroll
                for (int nt = 0; nt < 8; nt++)
#pragma unroll
                    for (int c = 0; c < 4; c++) {
                        int row = ib + mt * 16 + g + ((c >> 1) << 3);
                        int col = nt * 8 + tg * 2 + (c & 1);
                        if (r == 0) Qs[col * 68 + row] = oacc[mt][nt][c];
                        else        Qs[col * 68 + row] += oacc[mt][nt][c];
                    }
        }
        __syncthreads();
    }

    if (tid < 64) Lsm[tid] = 1.0f / Lsm[tid];
    __syncthreads();

    // ---- normalized, coalesced store [d][s]
    float* Ap = att + ((size_t)b * HID_ + h * D_) * S_ + i0;
    for (int v = tid; v < 1024; v += 256) {
        int d = v >> 4, iq = v & 15;
        float4 o = *(float4*)&Qs[d * 68 + iq * 4];
        o.x *= Lsm[iq * 4 + 0];
        o.y *= Lsm[iq * 4 + 1];
        o.z *= Lsm[iq * 4 + 2];
        o.w *= Lsm[iq * 4 + 3];
        *(float4*)(Ap + (size_t)d * S_ + iq * 4) = o;
    }
}

// ---------------------------------------------------------------------------
// Launch
// ---------------------------------------------------------------------------
extern "C" void kernel_launch(void* const* d_in, const int* in_sizes, int n_in,
                              void* d_out, int out_size)
{
    const float* x     = (const float*)d_in[0];
    const float* w_qkv = (const float*)d_in[1];
    const float* w_out = (const float*)d_in[2];
    const float* b_out = (const float*)d_in[3];
    float* out = (float*)d_out;

    float* qkv; cudaGetSymbolAddress((void**)&qkv, g_qkv);
    float* att; cudaGetSymbolAddress((void**)&att, g_att);

    static const size_t attn_smem = AT_SMEM_FLOATS * sizeof(float);  // ~88 KB
    cudaFuncSetAttribute(attn_tc_kernel,
                         cudaFuncAttributeMaxDynamicSharedMemorySize,
                         (int)attn_smem);

    init_tab_kernel<<<(S_ * 16 + 255) / 256, 256>>>();

    {   // QKV projection (bf16x3, fused RoPE on q/k tiles)
        dim3 grid(S_ / 128, O1_ / 64, B_);
        gemm_bf16_kernel<256, false, true><<<grid, 256>>>(w_qkv, x, nullptr, qkv, O1_);
    }

    l2norm_kernel<<<B_ * 2 * HID_, 256>>>(qkv);

    {   // Attention (2 blocks/SM + double-buffered cp.async)
        dim3 grid(S_ / 64, H_, B_);
        attn_tc_kernel<<<grid, 256, attn_smem>>>(qkv, att);
    }

    {   // Output projection (bf16x3 + bias)
        dim3 grid(S_ / 128, C_ / 64, B_);
        gemm_bf16_kernel<512, true, false><<<grid, 256>>>(w_out, att, b_out, out, C_);
    }
}